// round 10
// baseline (speedup 1.0000x reference)
#include <cuda_runtime.h>
#include <math.h>

#define NN 50000
#define EE 800000
#define NBLK 49
#define GEMM_HALF 782            // blocks per gemm half: 391 x-tiles x 2 y
#define PREP_BLKS 3125           // ceil(EE/256)

// ---------------- scratch (device globals; no allocations allowed) ----------------
__device__ float g_xw[(size_t)NN * 256];          // [N,256]: cols 0..127 hop0, 128..255 hop1
__device__ float g_as0[NN * 8], g_ad0[NN * 8], g_as1[NN * 8], g_ad1[NN * 8];
__device__ int g_src1[EE], g_dst1[EE], g_src2[EE], g_dst2[EE];
__device__ int g_deg1[NN], g_deg2[NN];
__device__ int g_start1[NN + 1], g_start2[NN + 1];
__device__ int g_cur1[NN], g_cur2[NN];
__device__ int g_csr1[EE], g_csr2[EE];
__device__ int g_bsum[2][64], g_boff[2][64];
__device__ int g_rowdone[NN];
__device__ int g_is64;

// ---------------- packed f32x2 FMA (Blackwell FFMA2, PTX-only) ----------------
__device__ __forceinline__ void ffma2(float2& d, float2 a, float2 b) {
    unsigned long long& dd = reinterpret_cast<unsigned long long&>(d);
    unsigned long long aa = reinterpret_cast<unsigned long long&>(a);
    unsigned long long bb = reinterpret_cast<unsigned long long&>(b);
    asm("fma.rn.f32x2 %0, %1, %2, %0;" : "+l"(dd) : "l"(aa), "l"(bb));
}

// ---------------- zero + edge-index dtype detection (fused) ----------------
__global__ void zero_kernel(const int* __restrict__ ei32) {
    int i = blockIdx.x * blockDim.x + threadIdx.x;
    if (i < NN) { g_deg1[i] = 0; g_deg2[i] = 0; g_cur1[i] = 0; g_cur2[i] = 0; g_rowdone[i] = 0; }
    if (blockIdx.x == 0 && threadIdx.x < 32) {
        int v = ei32[2 * threadIdx.x + 1];   // odd words 0 iff int64 (ids < 2^31)
        unsigned b = __ballot_sync(0xffffffffu, v != 0);
        if (threadIdx.x == 0) g_is64 = (b == 0) ? 1 : 0;
    }
}

// ---------------- GEMM block body (device function, called from fat kernels) ----------------
// tile 64(M) x 128(N), K-tile 32; 256 threads; fused attention logits epilogue
__device__ __forceinline__ void gemm_block(int bx, int by,
                                           const float* __restrict__ x,
                                           const float* __restrict__ W0,
                                           const float* __restrict__ W1,
                                           const float* __restrict__ as0,
                                           const float* __restrict__ ad0,
                                           const float* __restrict__ as1,
                                           const float* __restrict__ ad1) {
    __shared__ float As[32][68];
    __shared__ float Bs[32][132];
    const float* __restrict__ W = by ? W1 : W0;
    int rowbase = bx * 64;
    int coff = by * 128;
    int tid = threadIdx.x;
    int tx = tid & 15, ty = tid >> 4;
    int lane = tid & 31, warp = tid >> 5;
    int jb = tid & 127, kb0 = tid >> 7;

    float2 acc[4][4];
    #pragma unroll
    for (int i = 0; i < 4; i++)
        #pragma unroll
        for (int q = 0; q < 4; q++) acc[i][q] = make_float2(0.f, 0.f);

    for (int kb = 0; kb < 256; kb += 32) {
        #pragma unroll
        for (int r = warp; r < 64; r += 8) {
            int row = rowbase + r;
            As[lane][r] = (row < NN) ? x[(size_t)row * 256 + kb + lane] : 0.f;
        }
        #pragma unroll
        for (int k = kb0; k < 32; k += 2) {
            Bs[k][jb] = W[(size_t)(kb + k) * 128 + jb];
        }
        __syncthreads();
        #pragma unroll
        for (int kk = 0; kk < 32; kk++) {
            float4 b0 = *(const float4*)&Bs[kk][tx * 8];
            float4 b1 = *(const float4*)&Bs[kk][tx * 8 + 4];
            float2 bq0 = make_float2(b0.x, b0.y), bq1 = make_float2(b0.z, b0.w);
            float2 bq2 = make_float2(b1.x, b1.y), bq3 = make_float2(b1.z, b1.w);
            #pragma unroll
            for (int i = 0; i < 4; i++) {
                float a = As[kk][ty * 4 + i];
                float2 a2 = make_float2(a, a);
                ffma2(acc[i][0], a2, bq0);
                ffma2(acc[i][1], a2, bq1);
                ffma2(acc[i][2], a2, bq2);
                ffma2(acc[i][3], a2, bq3);
            }
        }
        __syncthreads();
    }

    const float* __restrict__ avs = by ? as1 : as0;
    const float* __restrict__ avd = by ? ad1 : ad0;
    float* __restrict__ gas = by ? g_as1 : g_as0;
    float* __restrict__ gad = by ? g_ad1 : g_ad0;
    int head = tx >> 1;
    int sub = (tx & 1) * 8;
    float4 v0 = *(const float4*)&avs[head * 16 + sub];
    float4 v1 = *(const float4*)&avs[head * 16 + sub + 4];
    float4 u0 = *(const float4*)&avd[head * 16 + sub];
    float4 u1 = *(const float4*)&avd[head * 16 + sub + 4];

    #pragma unroll
    for (int i = 0; i < 4; i++) {
        int row = rowbase + ty * 4 + i;
        float4 o0 = make_float4(acc[i][0].x, acc[i][0].y, acc[i][1].x, acc[i][1].y);
        float4 o1 = make_float4(acc[i][2].x, acc[i][2].y, acc[i][3].x, acc[i][3].y);
        if (row < NN) {
            *(float4*)&g_xw[(size_t)row * 256 + coff + tx * 8] = o0;
            *(float4*)&g_xw[(size_t)row * 256 + coff + tx * 8 + 4] = o1;
        }
        float s = o0.x * v0.x + o0.y * v0.y + o0.z * v0.z + o0.w * v0.w
                + o1.x * v1.x + o1.y * v1.y + o1.z * v1.z + o1.w * v1.w;
        float d = o0.x * u0.x + o0.y * u0.y + o0.z * u0.z + o0.w * u0.w
                + o1.x * u1.x + o1.y * u1.y + o1.z * u1.z + o1.w * u1.w;
        s += __shfl_xor_sync(0xffffffffu, s, 1);
        d += __shfl_xor_sync(0xffffffffu, d, 1);
        if ((tx & 1) == 0 && row < NN) {
            gas[row * 8 + head] = s;
            gad[row * 8 + head] = d;
        }
    }
}

// ---------------- prep body: edges + degree counts ----------------
__device__ __forceinline__ void prep_body(int blk, const void* __restrict__ ei) {
    int e = blk * 256 + threadIdx.x;
    if (e >= EE) return;
    int s, d, s2, d2;
    if (g_is64) {
        const long long* r = (const long long*)ei;
        s = (int)r[e]; d = (int)r[EE + e];
        s2 = (int)r[d]; d2 = (int)r[EE + d];
    } else {
        const int* r = (const int*)ei;
        s = r[e]; d = r[EE + e];
        s2 = r[d]; d2 = r[EE + d];
    }
    g_src1[e] = s; g_dst1[e] = d;
    g_src2[e] = s2; g_dst2[e] = d2;
    atomicAdd(&g_deg1[d], 1);
    atomicAdd(&g_deg2[d2], 1);
}

// ---------------- scatter body ----------------
__device__ __forceinline__ void scatter_body(int blk) {
    int e = blk * 256 + threadIdx.x;
    if (e >= EE) return;
    {
        int d = g_dst1[e];
        int slot = g_start1[d] + atomicAdd(&g_cur1[d], 1);
        g_csr1[slot] = g_src1[e];
    }
    {
        int d = g_dst2[e];
        int slot = g_start2[d] + atomicAdd(&g_cur2[d], 1);
        g_csr2[slot] = g_src2[e];
    }
}

// ---------------- fat kernels: gemm half + prep/scatter overlap ----------------
__global__ __launch_bounds__(256) void fat1_kernel(const float* __restrict__ x,
                                                   const float* __restrict__ W0,
                                                   const float* __restrict__ W1,
                                                   const float* __restrict__ as0,
                                                   const float* __restrict__ ad0,
                                                   const float* __restrict__ as1,
                                                   const float* __restrict__ ad1,
                                                   const void* __restrict__ ei) {
    if (blockIdx.x < GEMM_HALF)
        gemm_block(blockIdx.x >> 1, blockIdx.x & 1, x, W0, W1, as0, ad0, as1, ad1);
    else
        prep_body(blockIdx.x - GEMM_HALF, ei);
}

__global__ __launch_bounds__(256) void fat2_kernel(const float* __restrict__ x,
                                                   const float* __restrict__ W0,
                                                   const float* __restrict__ W1,
                                                   const float* __restrict__ as0,
                                                   const float* __restrict__ ad0,
                                                   const float* __restrict__ as1,
                                                   const float* __restrict__ ad1) {
    if (blockIdx.x < GEMM_HALF)
        gemm_block(391 + (blockIdx.x >> 1), blockIdx.x & 1, x, W0, W1, as0, ad0, as1, ad1);
    else
        scatter_body(blockIdx.x - GEMM_HALF);
}

// ---------------- 3-stage parallel exclusive scan ----------------
__global__ __launch_bounds__(1024) void scan1_kernel() {
    int arr = blockIdx.y;
    const int* __restrict__ deg = arr ? g_deg2 : g_deg1;
    int* __restrict__ start = arr ? g_start2 : g_start1;
    __shared__ int warpsum[32];
    int t = threadIdx.x, lane = t & 31, w = t >> 5;
    int i = blockIdx.x * 1024 + t;
    int v = (i < NN) ? deg[i] : 0;
    int incl = v;
    #pragma unroll
    for (int o = 1; o < 32; o <<= 1) {
        int u = __shfl_up_sync(0xffffffffu, incl, o);
        if (lane >= o) incl += u;
    }
    if (lane == 31) warpsum[w] = incl;
    __syncthreads();
    if (t < 32) {
        int ws = warpsum[t];
        int wi = ws;
        #pragma unroll
        for (int o = 1; o < 32; o <<= 1) {
            int u = __shfl_up_sync(0xffffffffu, wi, o);
            if (t >= o) wi += u;
        }
        warpsum[t] = wi - ws;
        if (t == 31) g_bsum[arr][blockIdx.x] = wi;
    }
    __syncthreads();
    if (i < NN) start[i] = warpsum[w] + incl - v;
}

__global__ void scan2_kernel() {
    __shared__ int sm[2][64];
    int t = threadIdx.x;
    int arr = t >> 6, i = t & 63;
    int v = (i < NBLK) ? g_bsum[arr][i] : 0;
    sm[arr][i] = v;
    __syncthreads();
    #pragma unroll
    for (int off = 1; off < 64; off <<= 1) {
        int add = (i >= off) ? sm[arr][i - off] : 0;
        __syncthreads();
        sm[arr][i] += add;
        __syncthreads();
    }
    g_boff[arr][i] = sm[arr][i] - v;
    if (i == 63) {
        if (arr == 0) g_start1[NN] = sm[0][63];
        else          g_start2[NN] = sm[1][63];
    }
}

__global__ __launch_bounds__(1024) void scan3_kernel() {
    int arr = blockIdx.y;
    int* __restrict__ start = arr ? g_start2 : g_start1;
    int i = blockIdx.x * 1024 + threadIdx.x;
    if (i < NN) start[i] += g_boff[arr][blockIdx.x];
}

// ---------------- warp-per-dst softmax+aggregation, fused residual+LayerNorm ----------------
// 8 warps/block, one (hop,dst) per warp. Self-loop lifted out of loops.
// selfmult: hop 1 = 1, hop 2 = 2 (reference double-appends self loops on hop 2).
// Per-ROW done counter: lane 0 of each hop-warp increments once; the warp observing
// prev==1 (both halves stored + fenced) performs residual+LayerNorm for the row.
__global__ __launch_bounds__(256) void agg_kernel(const float* __restrict__ b0,
                                                  const float* __restrict__ b1,
                                                  const float* __restrict__ x,
                                                  const float* __restrict__ gamma,
                                                  const float* __restrict__ beta,
                                                  float* __restrict__ out) {
    int gw = blockIdx.x * 8 + (threadIdx.x >> 5);
    if (gw >= 2 * NN) return;
    int hop = (gw >= NN) ? 1 : 0;
    int dst = gw - hop * NN;
    int lane = threadIdx.x & 31;
    const int* __restrict__ start = hop ? g_start2 : g_start1;
    const int* __restrict__ csr   = hop ? g_csr2 : g_csr1;
    const float* __restrict__ a_s = hop ? g_as1 : g_as0;
    const float* __restrict__ a_d = hop ? g_ad1 : g_ad0;
    const float* __restrict__ bias = hop ? b1 : b0;
    float selfmult = hop ? 2.0f : 1.0f;

    int s0 = start[dst];
    int deg = start[dst + 1] - s0;

    // pass 1: online softmax; lane = h + 8*j (8 heads x 4 edge-groups); self in j==0 init
    int h = lane & 7, j = lane >> 3;
    float ad_h = a_d[dst * 8 + h];
    float vself = a_s[dst * 8 + h] + ad_h;
    vself = vself > 0.f ? vself : 0.2f * vself;
    float m = (j == 0) ? vself : -1e30f;
    float sum = (j == 0) ? selfmult : 0.f;
    for (int e = j; e < deg; e += 4) {
        int src = csr[s0 + e];
        float v = a_s[src * 8 + h] + ad_h;
        v = v > 0.f ? v : 0.2f * v;
        float nm = fmaxf(m, v);
        sum = sum * __expf(m - nm) + __expf(v - nm);
        m = nm;
    }
    #pragma unroll
    for (int o = 8; o <= 16; o <<= 1) {
        float om = __shfl_xor_sync(0xffffffffu, m, o);
        float os = __shfl_xor_sync(0xffffffffu, sum, o);
        float nm = fmaxf(m, om);
        sum = sum * __expf(m - nm) + os * __expf(om - nm);
        m = nm;
    }

    // pass 2: lane owns channels [lane*4, lane*4+4) of this hop's 128; head = lane>>2
    int hh = lane >> 2;
    float mh = __shfl_sync(0xffffffffu, m, hh);
    float is = 1.f / __shfl_sync(0xffffffffu, sum, hh);
    float adh = __shfl_sync(0xffffffffu, ad_h, hh);
    int off4 = hop ? 32 : 0;
    const float4* __restrict__ xw4 = (const float4*)g_xw;
    float4 acc = make_float4(0.f, 0.f, 0.f, 0.f);
    #pragma unroll 2
    for (int e = 0; e < deg; e++) {
        int src = csr[s0 + e];
        float v = a_s[src * 8 + hh] + adh;
        v = v > 0.f ? v : 0.2f * v;
        float al = __expf(v - mh) * is;
        float4 f = xw4[(size_t)src * 64 + off4 + lane];
        acc.x += al * f.x; acc.y += al * f.y; acc.z += al * f.z; acc.w += al * f.w;
    }
    {   // self-loop term
        float v = a_s[dst * 8 + hh] + adh;
        v = v > 0.f ? v : 0.2f * v;
        float al = selfmult * __expf(v - mh) * is;
        float4 f = xw4[(size_t)dst * 64 + off4 + lane];
        acc.x += al * f.x; acc.y += al * f.y; acc.z += al * f.z; acc.w += al * f.w;
    }
    float4 bv = ((const float4*)bias)[lane];
    acc.x += bv.x; acc.y += bv.y; acc.z += bv.z; acc.w += bv.w;
    ((float4*)out)[(size_t)dst * 64 + off4 + lane] = acc;

    // fused residual + LayerNorm: per-warp handshake (lane 0 increments ONCE per warp).
    // release: every lane fences its own store, syncwarp, then lane 0 bumps the counter.
    __threadfence();
    __syncwarp();
    int prev = 0;
    if (lane == 0) prev = atomicAdd(&g_rowdone[dst], 1);
    prev = __shfl_sync(0xffffffffu, prev, 0);
    if (prev == 1) {
        __threadfence();                           // acquire: other warp's half now visible
        float4* o4 = (float4*)out;
        const float4* x4 = (const float4*)x;
        size_t base = (size_t)dst * 64 + lane * 2;
        float4 a0 = o4[base], a1 = o4[base + 1];
        float4 r0 = x4[base], r1 = x4[base + 1];
        a0.x += r0.x; a0.y += r0.y; a0.z += r0.z; a0.w += r0.w;
        a1.x += r1.x; a1.y += r1.y; a1.z += r1.z; a1.w += r1.w;
        float s = a0.x + a0.y + a0.z + a0.w + a1.x + a1.y + a1.z + a1.w;
        float q = a0.x * a0.x + a0.y * a0.y + a0.z * a0.z + a0.w * a0.w
                + a1.x * a1.x + a1.y * a1.y + a1.z * a1.z + a1.w * a1.w;
        #pragma unroll
        for (int o = 16; o; o >>= 1) {
            s += __shfl_xor_sync(0xffffffffu, s, o);
            q += __shfl_xor_sync(0xffffffffu, q, o);
        }
        float mu = s * (1.f / 256.f);
        float var = q * (1.f / 256.f) - mu * mu;
        float rs = rsqrtf(var + 1e-5f);
        const float4* g4 = (const float4*)gamma;
        const float4* be4 = (const float4*)beta;
        float4 ga = g4[lane * 2], gb = g4[lane * 2 + 1];
        float4 ba = be4[lane * 2], bb = be4[lane * 2 + 1];
        a0.x = (a0.x - mu) * rs * ga.x + ba.x; a0.y = (a0.y - mu) * rs * ga.y + ba.y;
        a0.z = (a0.z - mu) * rs * ga.z + ba.z; a0.w = (a0.w - mu) * rs * ga.w + ba.w;
        a1.x = (a1.x - mu) * rs * gb.x + bb.x; a1.y = (a1.y - mu) * rs * gb.y + bb.y;
        a1.z = (a1.z - mu) * rs * gb.z + bb.z; a1.w = (a1.w - mu) * rs * gb.w + bb.w;
        o4[base] = a0; o4[base + 1] = a1;
    }
}

// ---------------- launch ----------------
extern "C" void kernel_launch(void* const* d_in, const int* in_sizes, int n_in,
                              void* d_out, int out_size) {
    const float* x     = (const float*)d_in[0];
    const void*  ei    = d_in[1];
    const float* W0    = (const float*)d_in[2];
    const float* as0   = (const float*)d_in[3];
    const float* ad0   = (const float*)d_in[4];
    const float* b0    = (const float*)d_in[5];
    const float* W1    = (const float*)d_in[6];
    const float* as1   = (const float*)d_in[7];
    const float* ad1   = (const float*)d_in[8];
    const float* b1    = (const float*)d_in[9];
    const float* gamma = (const float*)d_in[10];
    const float* beta  = (const float*)d_in[11];
    float* out = (float*)d_out;

    zero_kernel<<<(NN + 255) / 256, 256>>>((const int*)ei);
    fat1_kernel<<<GEMM_HALF + PREP_BLKS, 256>>>(x, W0, W1, as0, ad0, as1, ad1, ei);
    scan1_kernel<<<dim3(NBLK, 2), 1024>>>();
    scan2_kernel<<<1, 128>>>();
    scan3_kernel<<<dim3(NBLK, 2), 1024>>>();
    fat2_kernel<<<GEMM_HALF + PREP_BLKS, 256>>>(x, W0, W1, as0, ad0, as1, ad1);
    agg_kernel<<<(2 * NN + 7) / 8, 256>>>(b0, b1, x, gamma, beta, out);
}

// round 11
// speedup vs baseline: 1.3898x; 1.3898x over previous
#include <cuda_runtime.h>
#include <cuda_bf16.h>
#include <math.h>

#define NN 50000
#define EE 800000
#define NBLK 49

// ---------------- scratch (device globals; no allocations allowed) ----------------
__device__ float g_xw[(size_t)NN * 256];          // [N,256]: cols 0..127 hop0, 128..255 hop1
__device__ float g_as0[NN * 8], g_ad0[NN * 8], g_as1[NN * 8], g_ad1[NN * 8];
__device__ int g_src1[EE], g_dst1[EE], g_src2[EE], g_dst2[EE];
__device__ int g_deg1[NN], g_deg2[NN];
__device__ int g_start1[NN + 1], g_start2[NN + 1];
__device__ int g_cur1[NN], g_cur2[NN];
__device__ int g_csr1[EE], g_csr2[EE];
__device__ int g_bsum[2][64], g_boff[2][64];
__device__ int g_rowdone[NN];
__device__ int g_is64;
// bf16 hi/lo splits: x rows [N][256], W as [n=256][k=256] (n = concat out-col)
__device__ uint4 g_xhi4[1601536], g_xlo4[1601536];
__device__ uint4 g_whi4[8192], g_wlo4[8192];

// ---------------- PTX helpers ----------------
__device__ __forceinline__ unsigned smem_to_u32(const void* p) {
    unsigned a;
    asm("{ .reg .u64 t; cvta.to.shared.u64 t, %1; cvt.u32.u64 %0, t; }" : "=r"(a) : "l"(p));
    return a;
}
__device__ __forceinline__ void ldsm_x4(unsigned* r, unsigned addr) {
    asm volatile("ldmatrix.sync.aligned.m8n8.x4.shared.b16 {%0,%1,%2,%3}, [%4];"
        : "=r"(r[0]), "=r"(r[1]), "=r"(r[2]), "=r"(r[3]) : "r"(addr));
}
__device__ __forceinline__ void mma_bf16(float* c, const unsigned* a, unsigned b0, unsigned b1) {
    asm volatile("mma.sync.aligned.m16n8k16.row.col.f32.bf16.bf16.f32 "
        "{%0,%1,%2,%3}, {%4,%5,%6,%7}, {%8,%9}, {%0,%1,%2,%3};"
        : "+f"(c[0]), "+f"(c[1]), "+f"(c[2]), "+f"(c[3])
        : "r"(a[0]), "r"(a[1]), "r"(a[2]), "r"(a[3]), "r"(b0), "r"(b1));
}

// ---------------- zero + edge-index dtype detection (fused) ----------------
__global__ void zero_kernel(const int* __restrict__ ei32) {
    int i = blockIdx.x * blockDim.x + threadIdx.x;
    if (i < NN) { g_deg1[i] = 0; g_deg2[i] = 0; g_cur1[i] = 0; g_cur2[i] = 0; g_rowdone[i] = 0; }
    if (blockIdx.x == 0 && threadIdx.x < 32) {
        int v = ei32[2 * threadIdx.x + 1];   // odd words 0 iff int64 (ids < 2^31)
        unsigned b = __ballot_sync(0xffffffffu, v != 0);
        if (threadIdx.x == 0) g_is64 = (b == 0) ? 1 : 0;
    }
}

// ---------------- bf16 hi/lo preconversion ----------------
__global__ void conv_x_kernel(const float* __restrict__ x) {
    int i = blockIdx.x * blockDim.x + threadIdx.x;     // 8 elems per thread
    if (i >= NN * 256 / 8) return;
    const float4* x4 = (const float4*)x;
    float4 a = x4[i * 2], b = x4[i * 2 + 1];
    float v[8] = {a.x, a.y, a.z, a.w, b.x, b.y, b.z, b.w};
    unsigned short hs[8], ls[8];
    #pragma unroll
    for (int j = 0; j < 8; j++) {
        __nv_bfloat16 h = __float2bfloat16(v[j]);
        __nv_bfloat16 l = __float2bfloat16(v[j] - __bfloat162float(h));
        hs[j] = __bfloat16_as_ushort(h);
        ls[j] = __bfloat16_as_ushort(l);
    }
    uint4 uh, ul;
    uh.x = hs[0] | ((unsigned)hs[1] << 16); uh.y = hs[2] | ((unsigned)hs[3] << 16);
    uh.z = hs[4] | ((unsigned)hs[5] << 16); uh.w = hs[6] | ((unsigned)hs[7] << 16);
    ul.x = ls[0] | ((unsigned)ls[1] << 16); ul.y = ls[2] | ((unsigned)ls[3] << 16);
    ul.z = ls[4] | ((unsigned)ls[5] << 16); ul.w = ls[6] | ((unsigned)ls[7] << 16);
    g_xhi4[i] = uh; g_xlo4[i] = ul;
}

__global__ void conv_w_kernel(const float* __restrict__ W0, const float* __restrict__ W1) {
    int idx = blockIdx.x * blockDim.x + threadIdx.x;   // 65536
    if (idx >= 256 * 256) return;
    int n = idx >> 8, k = idx & 255;
    float w = (n < 128) ? W0[k * 128 + n] : W1[k * 128 + (n - 128)];
    __nv_bfloat16 h = __float2bfloat16(w);
    __nv_bfloat16 l = __float2bfloat16(w - __bfloat162float(h));
    ((__nv_bfloat16*)g_whi4)[idx] = h;
    ((__nv_bfloat16*)g_wlo4)[idx] = l;
}

// ---------------- prep: edges + degree counts ----------------
__global__ void prep_kernel(const void* __restrict__ ei) {
    int e = blockIdx.x * blockDim.x + threadIdx.x;
    if (e >= EE) return;
    int s, d, s2, d2;
    if (g_is64) {
        const long long* r = (const long long*)ei;
        s = (int)r[e]; d = (int)r[EE + e];
        s2 = (int)r[d]; d2 = (int)r[EE + d];
    } else {
        const int* r = (const int*)ei;
        s = r[e]; d = r[EE + e];
        s2 = r[d]; d2 = r[EE + d];
    }
    g_src1[e] = s; g_dst1[e] = d;
    g_src2[e] = s2; g_dst2[e] = d2;
    atomicAdd(&g_deg1[d], 1);
    atomicAdd(&g_deg2[d2], 1);
}

// ---------------- 3-stage parallel exclusive scan ----------------
__global__ __launch_bounds__(1024) void scan1_kernel() {
    int arr = blockIdx.y;
    const int* __restrict__ deg = arr ? g_deg2 : g_deg1;
    int* __restrict__ start = arr ? g_start2 : g_start1;
    __shared__ int warpsum[32];
    int t = threadIdx.x, lane = t & 31, w = t >> 5;
    int i = blockIdx.x * 1024 + t;
    int v = (i < NN) ? deg[i] : 0;
    int incl = v;
    #pragma unroll
    for (int o = 1; o < 32; o <<= 1) {
        int u = __shfl_up_sync(0xffffffffu, incl, o);
        if (lane >= o) incl += u;
    }
    if (lane == 31) warpsum[w] = incl;
    __syncthreads();
    if (t < 32) {
        int ws = warpsum[t];
        int wi = ws;
        #pragma unroll
        for (int o = 1; o < 32; o <<= 1) {
            int u = __shfl_up_sync(0xffffffffu, wi, o);
            if (t >= o) wi += u;
        }
        warpsum[t] = wi - ws;
        if (t == 31) g_bsum[arr][blockIdx.x] = wi;
    }
    __syncthreads();
    if (i < NN) start[i] = warpsum[w] + incl - v;
}

__global__ void scan2_kernel() {
    __shared__ int sm[2][64];
    int t = threadIdx.x;
    int arr = t >> 6, i = t & 63;
    int v = (i < NBLK) ? g_bsum[arr][i] : 0;
    sm[arr][i] = v;
    __syncthreads();
    #pragma unroll
    for (int off = 1; off < 64; off <<= 1) {
        int add = (i >= off) ? sm[arr][i - off] : 0;
        __syncthreads();
        sm[arr][i] += add;
        __syncthreads();
    }
    g_boff[arr][i] = sm[arr][i] - v;
    if (i == 63) {
        if (arr == 0) g_start1[NN] = sm[0][63];
        else          g_start2[NN] = sm[1][63];
    }
}

__global__ __launch_bounds__(1024) void scan3_kernel() {
    int arr = blockIdx.y;
    int* __restrict__ start = arr ? g_start2 : g_start1;
    int i = blockIdx.x * 1024 + threadIdx.x;
    if (i < NN) start[i] += g_boff[arr][blockIdx.x];
}

__global__ void scatter_kernel() {
    int e = blockIdx.x * blockDim.x + threadIdx.x;
    if (e >= EE) return;
    {
        int d = g_dst1[e];
        int slot = g_start1[d] + atomicAdd(&g_cur1[d], 1);
        g_csr1[slot] = g_src1[e];
    }
    {
        int d = g_dst2[e];
        int slot = g_start2[d] + atomicAdd(&g_cur2[d], 1);
        g_csr2[slot] = g_src2[e];
    }
}

// ---------------- mma.sync bf16x3 GEMM: xw = x @ [W0|W1] + fused att logits --------------
// grid (391, 2): by = hop half. Block tile M=128 x N=128, 8 warps (16 rows each).
// K=256 in chunks of 32 (2 k16 steps). Passes: Ahi*Bhi + Ahi*Blo + Alo*Bhi (lo*lo dropped).
// smem stride 40 shorts (80B) -> ldmatrix row fetches hit all 32 banks exactly once.
__global__ __launch_bounds__(256) void gemm_mma_kernel(const float* __restrict__ as0,
                                                       const float* __restrict__ ad0,
                                                       const float* __restrict__ as1,
                                                       const float* __restrict__ ad1) {
    __shared__ __align__(16) unsigned short sAh[128 * 40], sAl[128 * 40];
    __shared__ __align__(16) unsigned short sBh[128 * 40], sBl[128 * 40];
    __shared__ float satt_s[128], satt_d[128];

    int tid = threadIdx.x;
    int w = tid >> 5, lane = tid & 31;
    int by = blockIdx.y;
    int rowbase = blockIdx.x * 128;

    // stage attention vectors for this hop (layout [head][16] == flat 128)
    {
        const float* __restrict__ avs = by ? as1 : as0;
        const float* __restrict__ avd = by ? ad1 : ad0;
        if (tid < 128) satt_s[tid] = avs[tid];
        else satt_d[tid - 128] = avd[tid - 128];
    }

    float acc[16][4];
    #pragma unroll
    for (int j = 0; j < 16; j++)
        #pragma unroll
        for (int q = 0; q < 4; q++) acc[j][q] = 0.f;

    unsigned baseAh = smem_to_u32(sAh), baseAl = smem_to_u32(sAl);
    unsigned baseBh = smem_to_u32(sBh), baseBl = smem_to_u32(sBl);

    // ldmatrix lane-address components
    int arow = w * 16 + (lane & 15);             // A rows within block tile
    int acolsel = (lane >> 4) << 3;              // +8 k for lanes 16-31
    int brow = (lane & 7) | ((lane >> 4) << 3);  // B n-row within n16 group
    int bcolsel = ((lane >> 3) & 1) << 3;        // +8 k for lanes 8-15, 24-31

    for (int kc = 0; kc < 256; kc += 32) {
        // load chunk: 512 uint4 per buffer (128 rows x 4 uint4)
        for (int i = tid; i < 512; i += 256) {
            int r = i >> 2, u = i & 3;
            int so = r * 40 + u * 8;             // shorts
            int rowg = rowbase + r;
            uint4 vh = make_uint4(0, 0, 0, 0), vl = make_uint4(0, 0, 0, 0);
            if (rowg < NN) {
                vh = g_xhi4[rowg * 32 + (kc >> 3) + u];
                vl = g_xlo4[rowg * 32 + (kc >> 3) + u];
            }
            *(uint4*)&sAh[so] = vh;
            *(uint4*)&sAl[so] = vl;
            int n = by * 128 + r;
            *(uint4*)&sBh[so] = g_whi4[n * 32 + (kc >> 3) + u];
            *(uint4*)&sBl[so] = g_wlo4[n * 32 + (kc >> 3) + u];
        }
        __syncthreads();
        #pragma unroll
        for (int ks = 0; ks < 32; ks += 16) {
            unsigned ah[4], al[4];
            unsigned aoff = (unsigned)((arow * 40 + ks + acolsel) * 2);
            ldsm_x4(ah, baseAh + aoff);
            ldsm_x4(al, baseAl + aoff);
            #pragma unroll
            for (int nt = 0; nt < 8; nt++) {
                unsigned bh[4], bl[4];
                unsigned boff = (unsigned)(((nt * 16 + brow) * 40 + ks + bcolsel) * 2);
                ldsm_x4(bh, baseBh + boff);
                ldsm_x4(bl, baseBl + boff);
                mma_bf16(acc[2 * nt],     ah, bh[0], bh[1]);
                mma_bf16(acc[2 * nt],     ah, bl[0], bl[1]);
                mma_bf16(acc[2 * nt],     al, bh[0], bh[1]);
                mma_bf16(acc[2 * nt + 1], ah, bh[2], bh[3]);
                mma_bf16(acc[2 * nt + 1], ah, bl[2], bl[3]);
                mma_bf16(acc[2 * nt + 1], al, bh[2], bh[3]);
            }
        }
        __syncthreads();
    }

    // epilogue: c0,c1 -> row g, cols j*8 + t*2,+1 ; c2,c3 -> row g+8
    int g = lane >> 2, t = lane & 3, t2 = t * 2;
    int r0 = rowbase + w * 16 + g;
    int r1 = r0 + 8;
    int coff = by * 128;
    if (r0 < NN) {
        #pragma unroll
        for (int j = 0; j < 16; j++)
            *(float2*)&g_xw[(size_t)r0 * 256 + coff + j * 8 + t2] = make_float2(acc[j][0], acc[j][1]);
    }
    if (r1 < NN) {
        #pragma unroll
        for (int j = 0; j < 16; j++)
            *(float2*)&g_xw[(size_t)r1 * 256 + coff + j * 8 + t2] = make_float2(acc[j][2], acc[j][3]);
    }
    // fused attention logits: per head h, cols = tiles 2h, 2h+1; reduce over 4 lanes (t)
    float* __restrict__ gas = by ? g_as1 : g_as0;
    float* __restrict__ gad = by ? g_ad1 : g_ad0;
    #pragma unroll
    for (int h = 0; h < 8; h++) {
        float vs0 = satt_s[16 * h + t2],     vs1 = satt_s[16 * h + t2 + 1];
        float vs2 = satt_s[16 * h + 8 + t2], vs3 = satt_s[16 * h + 8 + t2 + 1];
        float vd0 = satt_d[16 * h + t2],     vd1 = satt_d[16 * h + t2 + 1];
        float vd2 = satt_d[16 * h + 8 + t2], vd3 = satt_d[16 * h + 8 + t2 + 1];
        float s0 = acc[2*h][0]*vs0 + acc[2*h][1]*vs1 + acc[2*h+1][0]*vs2 + acc[2*h+1][1]*vs3;
        float d0 = acc[2*h][0]*vd0 + acc[2*h][1]*vd1 + acc[2*h+1][0]*vd2 + acc[2*h+1][1]*vd3;
        float s1 = acc[2*h][2]*vs0 + acc[2*h][3]*vs1 + acc[2*h+1][2]*vs2 + acc[2*h+1][3]*vs3;
        float d1 = acc[2*h][2]*vd0 + acc[2*h][3]*vd1 + acc[2*h+1][2]*vd2 + acc[2*h+1][3]*vd3;
        s0 += __shfl_xor_sync(0xffffffffu, s0, 1); s0 += __shfl_xor_sync(0xffffffffu, s0, 2);
        d0 += __shfl_xor_sync(0xffffffffu, d0, 1); d0 += __shfl_xor_sync(0xffffffffu, d0, 2);
        s1 += __shfl_xor_sync(0xffffffffu, s1, 1); s1 += __shfl_xor_sync(0xffffffffu, s1, 2);
        d1 += __shfl_xor_sync(0xffffffffu, d1, 1); d1 += __shfl_xor_sync(0xffffffffu, d1, 2);
        if (t == 0) {
            if (r0 < NN) { gas[r0 * 8 + h] = s0; gad[r0 * 8 + h] = d0; }
            if (r1 < NN) { gas[r1 * 8 + h] = s1; gad[r1 * 8 + h] = d1; }
        }
    }
}

// ---------------- warp-per-dst softmax+aggregation, fused residual+LayerNorm ----------------
// 8 warps/block, one (hop,dst) per warp. selfmult: hop2 = 2 (ref double-appends self loops).
__global__ __launch_bounds__(256) void agg_kernel(const float* __restrict__ b0,
                                                  const float* __restrict__ b1,
                                                  const float* __restrict__ x,
                                                  const float* __restrict__ gamma,
                                                  const float* __restrict__ beta,
                                                  float* __restrict__ out) {
    int gw = blockIdx.x * 8 + (threadIdx.x >> 5);
    if (gw >= 2 * NN) return;
    int hop = (gw >= NN) ? 1 : 0;
    int dst = gw - hop * NN;
    int lane = threadIdx.x & 31;
    const int* __restrict__ start = hop ? g_start2 : g_start1;
    const int* __restrict__ csr   = hop ? g_csr2 : g_csr1;
    const float* __restrict__ a_s = hop ? g_as1 : g_as0;
    const float* __restrict__ a_d = hop ? g_ad1 : g_ad0;
    const float* __restrict__ bias = hop ? b1 : b0;
    float selfmult = hop ? 2.0f : 1.0f;

    int s0 = start[dst];
    int deg = start[dst + 1] - s0;

    int h = lane & 7, j = lane >> 3;
    float ad_h = a_d[dst * 8 + h];
    float vself = a_s[dst * 8 + h] + ad_h;
    vself = vself > 0.f ? vself : 0.2f * vself;
    float m = (j == 0) ? vself : -1e30f;
    float sum = (j == 0) ? selfmult : 0.f;
    for (int e = j; e < deg; e += 4) {
        int src = csr[s0 + e];
        float v = a_s[src * 8 + h] + ad_h;
        v = v > 0.f ? v : 0.2f * v;
        float nm = fmaxf(m, v);
        sum = sum * __expf(m - nm) + __expf(v - nm);
        m = nm;
    }
    #pragma unroll
    for (int o = 8; o <= 16; o <<= 1) {
        float om = __shfl_xor_sync(0xffffffffu, m, o);
        float os = __shfl_xor_sync(0xffffffffu, sum, o);
        float nm = fmaxf(m, om);
        sum = sum * __expf(m - nm) + os * __expf(om - nm);
        m = nm;
    }

    int hh = lane >> 2;
    float mh = __shfl_sync(0xffffffffu, m, hh);
    float is = 1.f / __shfl_sync(0xffffffffu, sum, hh);
    float adh = __shfl_sync(0xffffffffu, ad_h, hh);
    int off4 = hop ? 32 : 0;
    const float4* __restrict__ xw4 = (const float4*)g_xw;
    float4 acc = make_float4(0.f, 0.f, 0.f, 0.f);
    #pragma unroll 2
    for (int e = 0; e < deg; e++) {
        int src = csr[s0 + e];
        float v = a_s[src * 8 + hh] + adh;
        v = v > 0.f ? v : 0.2f * v;
        float al = __expf(v - mh) * is;
        float4 f = xw4[(size_t)src * 64 + off4 + lane];
        acc.x += al * f.x; acc.y += al * f.y; acc.z += al * f.z; acc.w += al * f.w;
    }
    {
        float v = a_s[dst * 8 + hh] + adh;
        v = v > 0.f ? v : 0.2f * v;
        float al = selfmult * __expf(v - mh) * is;
        float4 f = xw4[(size_t)dst * 64 + off4 + lane];
        acc.x += al * f.x; acc.y += al * f.y; acc.z += al * f.z; acc.w += al * f.w;
    }
    float4 bv = ((const float4*)bias)[lane];
    acc.x += bv.x; acc.y += bv.y; acc.z += bv.z; acc.w += bv.w;
    ((float4*)out)[(size_t)dst * 64 + off4 + lane] = acc;

    // fused residual + LayerNorm: per-warp handshake (lane 0 increments once per warp)
    __threadfence();
    __syncwarp();
    int prev = 0;
    if (lane == 0) prev = atomicAdd(&g_rowdone[dst], 1);
    prev = __shfl_sync(0xffffffffu, prev, 0);
    if (prev == 1) {
        __threadfence();
        float4* o4 = (float4*)out;
        const float4* x4 = (const float4*)x;
        size_t base = (size_t)dst * 64 + lane * 2;
        float4 a0 = o4[base], a1 = o4[base + 1];
        float4 r0 = x4[base], r1 = x4[base + 1];
        a0.x += r0.x; a0.y += r0.y; a0.z += r0.z; a0.w += r0.w;
        a1.x += r1.x; a1.y += r1.y; a1.z += r1.z; a1.w += r1.w;
        float s = a0.x + a0.y + a0.z + a0.w + a1.x + a1.y + a1.z + a1.w;
        float q = a0.x * a0.x + a0.y * a0.y + a0.z * a0.z + a0.w * a0.w
                + a1.x * a1.x + a1.y * a1.y + a1.z * a1.z + a1.w * a1.w;
        #pragma unroll
        for (int o = 16; o; o >>= 1) {
            s += __shfl_xor_sync(0xffffffffu, s, o);
            q += __shfl_xor_sync(0xffffffffu, q, o);
        }
        float mu = s * (1.f / 256.f);
        float var = q * (1.f / 256.f) - mu * mu;
        float rs = rsqrtf(var + 1e-5f);
        const float4* g4 = (const float4*)gamma;
        const float4* be4 = (const float4*)beta;
        float4 ga = g4[lane * 2], gb = g4[lane * 2 + 1];
        float4 ba = be4[lane * 2], bb = be4[lane * 2 + 1];
        a0.x = (a0.x - mu) * rs * ga.x + ba.x; a0.y = (a0.y - mu) * rs * ga.y + ba.y;
        a0.z = (a0.z - mu) * rs * ga.z + ba.z; a0.w = (a0.w - mu) * rs * ga.w + ba.w;
        a1.x = (a1.x - mu) * rs * gb.x + bb.x; a1.y = (a1.y - mu) * rs * gb.y + bb.y;
        a1.z = (a1.z - mu) * rs * gb.z + bb.z; a1.w = (a1.w - mu) * rs * gb.w + bb.w;
        o4[base] = a0; o4[base + 1] = a1;
    }
}

// ---------------- launch ----------------
extern "C" void kernel_launch(void* const* d_in, const int* in_sizes, int n_in,
                              void* d_out, int out_size) {
    const float* x     = (const float*)d_in[0];
    const void*  ei    = d_in[1];
    const float* W0    = (const float*)d_in[2];
    const float* as0   = (const float*)d_in[3];
    const float* ad0   = (const float*)d_in[4];
    const float* b0    = (const float*)d_in[5];
    const float* W1    = (const float*)d_in[6];
    const float* as1   = (const float*)d_in[7];
    const float* ad1   = (const float*)d_in[8];
    const float* b1    = (const float*)d_in[9];
    const float* gamma = (const float*)d_in[10];
    const float* beta  = (const float*)d_in[11];
    float* out = (float*)d_out;

    zero_kernel<<<(NN + 255) / 256, 256>>>((const int*)ei);
    conv_w_kernel<<<(256 * 256 + 255) / 256, 256>>>(W0, W1);
    conv_x_kernel<<<(NN * 256 / 8 + 255) / 256, 256>>>(x);
    prep_kernel<<<(EE + 255) / 256, 256>>>(ei);
    scan1_kernel<<<dim3(NBLK, 2), 1024>>>();
    scan2_kernel<<<1, 128>>>();
    scan3_kernel<<<dim3(NBLK, 2), 1024>>>();
    scatter_kernel<<<(EE + 255) / 256, 256>>>();
    gemm_mma_kernel<<<dim3(391, 2), 256>>>(as0, ad0, as1, ad1);
    agg_kernel<<<(2 * NN + 7) / 8, 256>>>(b0, b1, x, gamma, beta, out);
}

// round 12
// speedup vs baseline: 1.5724x; 1.1314x over previous
#include <cuda_runtime.h>
#include <cuda_bf16.h>
#include <math.h>

#define NN 50000
#define EE 800000
#define NBLK 49
#define CAP 96

// ---------------- scratch (device globals; no allocations allowed) ----------------
__device__ float g_xw[(size_t)NN * 256];          // [N,256]: cols 0..127 hop0, 128..255 hop1
__device__ float g_as0[NN * 8], g_ad0[NN * 8], g_as1[NN * 8], g_ad1[NN * 8];
__device__ int g_src1[EE], g_dst1[EE], g_src2[EE], g_dst2[EE];
__device__ int g_deg1[NN], g_deg2[NN];
__device__ int g_start1[NN + 1], g_start2[NN + 1];
__device__ int g_cur1[NN], g_cur2[NN];
__device__ int g_csr1[EE], g_csr2[EE];
__device__ int g_bsum[2][64], g_boff[2][64];
__device__ int g_rowdone[NN];
__device__ int g_is64;
// bf16 hi/lo splits: x rows [N][256], W as [n=256][k=256] (n = concat out-col)
__device__ uint4 g_xhi4[1601536], g_xlo4[1601536];
__device__ uint4 g_whi4[8192], g_wlo4[8192];

// ---------------- PTX helpers ----------------
__device__ __forceinline__ unsigned smem_to_u32(const void* p) {
    unsigned a;
    asm("{ .reg .u64 t; cvta.to.shared.u64 t, %1; cvt.u32.u64 %0, t; }" : "=r"(a) : "l"(p));
    return a;
}
__device__ __forceinline__ void ldsm_x4(unsigned* r, unsigned addr) {
    asm volatile("ldmatrix.sync.aligned.m8n8.x4.shared.b16 {%0,%1,%2,%3}, [%4];"
        : "=r"(r[0]), "=r"(r[1]), "=r"(r[2]), "=r"(r[3]) : "r"(addr));
}
__device__ __forceinline__ void mma_bf16(float* c, const unsigned* a, unsigned b0, unsigned b1) {
    asm volatile("mma.sync.aligned.m16n8k16.row.col.f32.bf16.bf16.f32 "
        "{%0,%1,%2,%3}, {%4,%5,%6,%7}, {%8,%9}, {%0,%1,%2,%3};"
        : "+f"(c[0]), "+f"(c[1]), "+f"(c[2]), "+f"(c[3])
        : "r"(a[0]), "r"(a[1]), "r"(a[2]), "r"(a[3]), "r"(b0), "r"(b1));
}

// ---------------- zero + edge-index dtype detection (fused) ----------------
__global__ void zero_kernel(const int* __restrict__ ei32) {
    int i = blockIdx.x * blockDim.x + threadIdx.x;
    if (i < NN) { g_deg1[i] = 0; g_deg2[i] = 0; g_cur1[i] = 0; g_cur2[i] = 0; g_rowdone[i] = 0; }
    if (blockIdx.x == 0 && threadIdx.x < 32) {
        int v = ei32[2 * threadIdx.x + 1];   // odd words 0 iff int64 (ids < 2^31)
        unsigned b = __ballot_sync(0xffffffffu, v != 0);
        if (threadIdx.x == 0) g_is64 = (b == 0) ? 1 : 0;
    }
}

// ---------------- bf16 hi/lo preconversion ----------------
__global__ void conv_x_kernel(const float* __restrict__ x) {
    int i = blockIdx.x * blockDim.x + threadIdx.x;     // 8 elems per thread
    if (i >= NN * 256 / 8) return;
    const float4* x4 = (const float4*)x;
    float4 a = x4[i * 2], b = x4[i * 2 + 1];
    float v[8] = {a.x, a.y, a.z, a.w, b.x, b.y, b.z, b.w};
    unsigned short hs[8], ls[8];
    #pragma unroll
    for (int j = 0; j < 8; j++) {
        __nv_bfloat16 h = __float2bfloat16(v[j]);
        __nv_bfloat16 l = __float2bfloat16(v[j] - __bfloat162float(h));
        hs[j] = __bfloat16_as_ushort(h);
        ls[j] = __bfloat16_as_ushort(l);
    }
    uint4 uh, ul;
    uh.x = hs[0] | ((unsigned)hs[1] << 16); uh.y = hs[2] | ((unsigned)hs[3] << 16);
    uh.z = hs[4] | ((unsigned)hs[5] << 16); uh.w = hs[6] | ((unsigned)hs[7] << 16);
    ul.x = ls[0] | ((unsigned)ls[1] << 16); ul.y = ls[2] | ((unsigned)ls[3] << 16);
    ul.z = ls[4] | ((unsigned)ls[5] << 16); ul.w = ls[6] | ((unsigned)ls[7] << 16);
    g_xhi4[i] = uh; g_xlo4[i] = ul;
}

__global__ void conv_w_kernel(const float* __restrict__ W0, const float* __restrict__ W1) {
    int idx = blockIdx.x * blockDim.x + threadIdx.x;   // 65536
    if (idx >= 256 * 256) return;
    int n = idx >> 8, k = idx & 255;
    float w = (n < 128) ? W0[k * 128 + n] : W1[k * 128 + (n - 128)];
    __nv_bfloat16 h = __float2bfloat16(w);
    __nv_bfloat16 l = __float2bfloat16(w - __bfloat162float(h));
    ((__nv_bfloat16*)g_whi4)[idx] = h;
    ((__nv_bfloat16*)g_wlo4)[idx] = l;
}

// ---------------- prep: edges + degree counts ----------------
__global__ void prep_kernel(const void* __restrict__ ei) {
    int e = blockIdx.x * blockDim.x + threadIdx.x;
    if (e >= EE) return;
    int s, d, s2, d2;
    if (g_is64) {
        const long long* r = (const long long*)ei;
        s = (int)r[e]; d = (int)r[EE + e];
        s2 = (int)r[d]; d2 = (int)r[EE + d];
    } else {
        const int* r = (const int*)ei;
        s = r[e]; d = r[EE + e];
        s2 = r[d]; d2 = r[EE + d];
    }
    g_src1[e] = s; g_dst1[e] = d;
    g_src2[e] = s2; g_dst2[e] = d2;
    atomicAdd(&g_deg1[d], 1);
    atomicAdd(&g_deg2[d2], 1);
}

// ---------------- 3-stage parallel exclusive scan ----------------
__global__ __launch_bounds__(1024) void scan1_kernel() {
    int arr = blockIdx.y;
    const int* __restrict__ deg = arr ? g_deg2 : g_deg1;
    int* __restrict__ start = arr ? g_start2 : g_start1;
    __shared__ int warpsum[32];
    int t = threadIdx.x, lane = t & 31, w = t >> 5;
    int i = blockIdx.x * 1024 + t;
    int v = (i < NN) ? deg[i] : 0;
    int incl = v;
    #pragma unroll
    for (int o = 1; o < 32; o <<= 1) {
        int u = __shfl_up_sync(0xffffffffu, incl, o);
        if (lane >= o) incl += u;
    }
    if (lane == 31) warpsum[w] = incl;
    __syncthreads();
    if (t < 32) {
        int ws = warpsum[t];
        int wi = ws;
        #pragma unroll
        for (int o = 1; o < 32; o <<= 1) {
            int u = __shfl_up_sync(0xffffffffu, wi, o);
            if (t >= o) wi += u;
        }
        warpsum[t] = wi - ws;
        if (t == 31) g_bsum[arr][blockIdx.x] = wi;
    }
    __syncthreads();
    if (i < NN) start[i] = warpsum[w] + incl - v;
}

__global__ void scan2_kernel() {
    __shared__ int sm[2][64];
    int t = threadIdx.x;
    int arr = t >> 6, i = t & 63;
    int v = (i < NBLK) ? g_bsum[arr][i] : 0;
    sm[arr][i] = v;
    __syncthreads();
    #pragma unroll
    for (int off = 1; off < 64; off <<= 1) {
        int add = (i >= off) ? sm[arr][i - off] : 0;
        __syncthreads();
        sm[arr][i] += add;
        __syncthreads();
    }
    g_boff[arr][i] = sm[arr][i] - v;
    if (i == 63) {
        if (arr == 0) g_start1[NN] = sm[0][63];
        else          g_start2[NN] = sm[1][63];
    }
}

__global__ __launch_bounds__(1024) void scan3_kernel() {
    int arr = blockIdx.y;
    int* __restrict__ start = arr ? g_start2 : g_start1;
    int i = blockIdx.x * 1024 + threadIdx.x;
    if (i < NN) start[i] += g_boff[arr][blockIdx.x];
}

__global__ void scatter_kernel() {
    int e = blockIdx.x * blockDim.x + threadIdx.x;
    if (e >= EE) return;
    {
        int d = g_dst1[e];
        int slot = g_start1[d] + atomicAdd(&g_cur1[d], 1);
        g_csr1[slot] = g_src1[e];
    }
    {
        int d = g_dst2[e];
        int slot = g_start2[d] + atomicAdd(&g_cur2[d], 1);
        g_csr2[slot] = g_src2[e];
    }
}

// ---------------- mma.sync bf16x3 GEMM: xw = x @ [W0|W1] + fused att logits --------------
__global__ __launch_bounds__(256) void gemm_mma_kernel(const float* __restrict__ as0,
                                                       const float* __restrict__ ad0,
                                                       const float* __restrict__ as1,
                                                       const float* __restrict__ ad1) {
    __shared__ __align__(16) unsigned short sAh[128 * 40], sAl[128 * 40];
    __shared__ __align__(16) unsigned short sBh[128 * 40], sBl[128 * 40];
    __shared__ float satt_s[128], satt_d[128];

    int tid = threadIdx.x;
    int w = tid >> 5, lane = tid & 31;
    int by = blockIdx.y;
    int rowbase = blockIdx.x * 128;

    {
        const float* __restrict__ avs = by ? as1 : as0;
        const float* __restrict__ avd = by ? ad1 : ad0;
        if (tid < 128) satt_s[tid] = avs[tid];
        else satt_d[tid - 128] = avd[tid - 128];
    }

    float acc[16][4];
    #pragma unroll
    for (int j = 0; j < 16; j++)
        #pragma unroll
        for (int q = 0; q < 4; q++) acc[j][q] = 0.f;

    unsigned baseAh = smem_to_u32(sAh), baseAl = smem_to_u32(sAl);
    unsigned baseBh = smem_to_u32(sBh), baseBl = smem_to_u32(sBl);

    int arow = w * 16 + (lane & 15);
    int acolsel = (lane >> 4) << 3;
    int brow = (lane & 7) | ((lane >> 4) << 3);
    int bcolsel = ((lane >> 3) & 1) << 3;

    for (int kc = 0; kc < 256; kc += 32) {
        for (int i = tid; i < 512; i += 256) {
            int r = i >> 2, u = i & 3;
            int so = r * 40 + u * 8;
            int rowg = rowbase + r;
            uint4 vh = make_uint4(0, 0, 0, 0), vl = make_uint4(0, 0, 0, 0);
            if (rowg < NN) {
                vh = g_xhi4[rowg * 32 + (kc >> 3) + u];
                vl = g_xlo4[rowg * 32 + (kc >> 3) + u];
            }
            *(uint4*)&sAh[so] = vh;
            *(uint4*)&sAl[so] = vl;
            int n = by * 128 + r;
            *(uint4*)&sBh[so] = g_whi4[n * 32 + (kc >> 3) + u];
            *(uint4*)&sBl[so] = g_wlo4[n * 32 + (kc >> 3) + u];
        }
        __syncthreads();
        #pragma unroll
        for (int ks = 0; ks < 32; ks += 16) {
            unsigned ah[4], al[4];
            unsigned aoff = (unsigned)((arow * 40 + ks + acolsel) * 2);
            ldsm_x4(ah, baseAh + aoff);
            ldsm_x4(al, baseAl + aoff);
            #pragma unroll
            for (int nt = 0; nt < 8; nt++) {
                unsigned bh[4], bl[4];
                unsigned boff = (unsigned)(((nt * 16 + brow) * 40 + ks + bcolsel) * 2);
                ldsm_x4(bh, baseBh + boff);
                ldsm_x4(bl, baseBl + boff);
                mma_bf16(acc[2 * nt],     ah, bh[0], bh[1]);
                mma_bf16(acc[2 * nt],     ah, bl[0], bl[1]);
                mma_bf16(acc[2 * nt],     al, bh[0], bh[1]);
                mma_bf16(acc[2 * nt + 1], ah, bh[2], bh[3]);
                mma_bf16(acc[2 * nt + 1], ah, bl[2], bl[3]);
                mma_bf16(acc[2 * nt + 1], al, bh[2], bh[3]);
            }
        }
        __syncthreads();
    }

    int g = lane >> 2, t = lane & 3, t2 = t * 2;
    int r0 = rowbase + w * 16 + g;
    int r1 = r0 + 8;
    int coff = by * 128;
    if (r0 < NN) {
        #pragma unroll
        for (int j = 0; j < 16; j++)
            *(float2*)&g_xw[(size_t)r0 * 256 + coff + j * 8 + t2] = make_float2(acc[j][0], acc[j][1]);
    }
    if (r1 < NN) {
        #pragma unroll
        for (int j = 0; j < 16; j++)
            *(float2*)&g_xw[(size_t)r1 * 256 + coff + j * 8 + t2] = make_float2(acc[j][2], acc[j][3]);
    }
    float* __restrict__ gas = by ? g_as1 : g_as0;
    float* __restrict__ gad = by ? g_ad1 : g_ad0;
    #pragma unroll
    for (int h = 0; h < 8; h++) {
        float vs0 = satt_s[16 * h + t2],     vs1 = satt_s[16 * h + t2 + 1];
        float vs2 = satt_s[16 * h + 8 + t2], vs3 = satt_s[16 * h + 8 + t2 + 1];
        float vd0 = satt_d[16 * h + t2],     vd1 = satt_d[16 * h + t2 + 1];
        float vd2 = satt_d[16 * h + 8 + t2], vd3 = satt_d[16 * h + 8 + t2 + 1];
        float s0 = acc[2*h][0]*vs0 + acc[2*h][1]*vs1 + acc[2*h+1][0]*vs2 + acc[2*h+1][1]*vs3;
        float d0 = acc[2*h][0]*vd0 + acc[2*h][1]*vd1 + acc[2*h+1][0]*vd2 + acc[2*h+1][1]*vd3;
        float s1 = acc[2*h][2]*vs0 + acc[2*h][3]*vs1 + acc[2*h+1][2]*vs2 + acc[2*h+1][3]*vs3;
        float d1 = acc[2*h][2]*vd0 + acc[2*h][3]*vd1 + acc[2*h+1][2]*vd2 + acc[2*h+1][3]*vd3;
        s0 += __shfl_xor_sync(0xffffffffu, s0, 1); s0 += __shfl_xor_sync(0xffffffffu, s0, 2);
        d0 += __shfl_xor_sync(0xffffffffu, d0, 1); d0 += __shfl_xor_sync(0xffffffffu, d0, 2);
        s1 += __shfl_xor_sync(0xffffffffu, s1, 1); s1 += __shfl_xor_sync(0xffffffffu, s1, 2);
        d1 += __shfl_xor_sync(0xffffffffu, d1, 1); d1 += __shfl_xor_sync(0xffffffffu, d1, 2);
        if (t == 0) {
            if (r0 < NN) { gas[r0 * 8 + h] = s0; gad[r0 * 8 + h] = d0; }
            if (r1 < NN) { gas[r1 * 8 + h] = s1; gad[r1 * 8 + h] = d1; }
        }
    }
}

// ---------------- warp-per-dst softmax+aggregation, smem-cached, fused LN ----------------
// 8 warps/block, one (hop,dst) per warp. selfmult: hop2 = 2 (ref double-appends self loops).
// deg <= CAP: csr srcs + per-(edge,head) logits cached in smem -> pass 2 has no dependent
// gathers (only the independent xw float4 gather, batched x4 for MLP). deg > CAP: generic.
__global__ __launch_bounds__(256) void agg_kernel(const float* __restrict__ b0,
                                                  const float* __restrict__ b1,
                                                  const float* __restrict__ x,
                                                  const float* __restrict__ gamma,
                                                  const float* __restrict__ beta,
                                                  float* __restrict__ out) {
    __shared__ int   scache[8][CAP];
    __shared__ float lcache[8][CAP][8];
    int w = threadIdx.x >> 5;
    int gw = blockIdx.x * 8 + w;
    if (gw >= 2 * NN) return;
    int hop = (gw >= NN) ? 1 : 0;
    int dst = gw - hop * NN;
    int lane = threadIdx.x & 31;
    const int* __restrict__ start = hop ? g_start2 : g_start1;
    const int* __restrict__ csr   = hop ? g_csr2 : g_csr1;
    const float* __restrict__ a_s = hop ? g_as1 : g_as0;
    const float* __restrict__ a_d = hop ? g_ad1 : g_ad0;
    const float* __restrict__ bias = hop ? b1 : b0;
    float selfmult = hop ? 2.0f : 1.0f;

    int s0 = start[dst];
    int deg = start[dst + 1] - s0;
    bool cached = (deg <= CAP);

    int h = lane & 7, j = lane >> 3;
    float ad_h = a_d[dst * 8 + h];
    float vself = a_s[dst * 8 + h] + ad_h;
    vself = vself > 0.f ? vself : 0.2f * vself;
    float m = (j == 0) ? vself : -1e30f;
    float sum = (j == 0) ? selfmult : 0.f;

    if (cached) {
        for (int e = lane; e < deg; e += 32) scache[w][e] = csr[s0 + e];
        __syncwarp();
        for (int e = j; e < deg; e += 4) {
            int src = scache[w][e];
            float v = a_s[src * 8 + h] + ad_h;
            v = v > 0.f ? v : 0.2f * v;
            lcache[w][e][h] = v;
            float nm = fmaxf(m, v);
            sum = sum * __expf(m - nm) + __expf(v - nm);
            m = nm;
        }
        __syncwarp();
    } else {
        for (int e = j; e < deg; e += 4) {
            int src = csr[s0 + e];
            float v = a_s[src * 8 + h] + ad_h;
            v = v > 0.f ? v : 0.2f * v;
            float nm = fmaxf(m, v);
            sum = sum * __expf(m - nm) + __expf(v - nm);
            m = nm;
        }
    }
    #pragma unroll
    for (int o = 8; o <= 16; o <<= 1) {
        float om = __shfl_xor_sync(0xffffffffu, m, o);
        float os = __shfl_xor_sync(0xffffffffu, sum, o);
        float nm = fmaxf(m, om);
        sum = sum * __expf(m - nm) + os * __expf(om - nm);
        m = nm;
    }

    int hh = lane >> 2;
    float mh = __shfl_sync(0xffffffffu, m, hh);
    float is = 1.f / __shfl_sync(0xffffffffu, sum, hh);
    float adh = __shfl_sync(0xffffffffu, ad_h, hh);
    int off4 = hop ? 32 : 0;
    const float4* __restrict__ xw4 = (const float4*)g_xw;
    float4 acc = make_float4(0.f, 0.f, 0.f, 0.f);

    if (cached) {
        int e = 0;
        for (; e + 4 <= deg; e += 4) {
            int sA = scache[w][e],     sB = scache[w][e + 1];
            int sC = scache[w][e + 2], sD = scache[w][e + 3];
            float vA = lcache[w][e][hh],     vB = lcache[w][e + 1][hh];
            float vC = lcache[w][e + 2][hh], vD = lcache[w][e + 3][hh];
            float4 fA = xw4[(size_t)sA * 64 + off4 + lane];
            float4 fB = xw4[(size_t)sB * 64 + off4 + lane];
            float4 fC = xw4[(size_t)sC * 64 + off4 + lane];
            float4 fD = xw4[(size_t)sD * 64 + off4 + lane];
            float aA = __expf(vA - mh) * is, aB = __expf(vB - mh) * is;
            float aC = __expf(vC - mh) * is, aD = __expf(vD - mh) * is;
            acc.x += aA * fA.x; acc.y += aA * fA.y; acc.z += aA * fA.z; acc.w += aA * fA.w;
            acc.x += aB * fB.x; acc.y += aB * fB.y; acc.z += aB * fB.z; acc.w += aB * fB.w;
            acc.x += aC * fC.x; acc.y += aC * fC.y; acc.z += aC * fC.z; acc.w += aC * fC.w;
            acc.x += aD * fD.x; acc.y += aD * fD.y; acc.z += aD * fD.z; acc.w += aD * fD.w;
        }
        for (; e < deg; e++) {
            int src = scache[w][e];
            float v = lcache[w][e][hh];
            float al = __expf(v - mh) * is;
            float4 f = xw4[(size_t)src * 64 + off4 + lane];
            acc.x += al * f.x; acc.y += al * f.y; acc.z += al * f.z; acc.w += al * f.w;
        }
    } else {
        #pragma unroll 2
        for (int e = 0; e < deg; e++) {
            int src = csr[s0 + e];
            float v = a_s[src * 8 + hh] + adh;
            v = v > 0.f ? v : 0.2f * v;
            float al = __expf(v - mh) * is;
            float4 f = xw4[(size_t)src * 64 + off4 + lane];
            acc.x += al * f.x; acc.y += al * f.y; acc.z += al * f.z; acc.w += al * f.w;
        }
    }
    {   // self-loop term
        float v = a_s[dst * 8 + hh] + adh;
        v = v > 0.f ? v : 0.2f * v;
        float al = selfmult * __expf(v - mh) * is;
        float4 f = xw4[(size_t)dst * 64 + off4 + lane];
        acc.x += al * f.x; acc.y += al * f.y; acc.z += al * f.z; acc.w += al * f.w;
    }
    float4 bv = ((const float4*)bias)[lane];
    acc.x += bv.x; acc.y += bv.y; acc.z += bv.z; acc.w += bv.w;
    ((float4*)out)[(size_t)dst * 64 + off4 + lane] = acc;

    // fused residual + LayerNorm: per-warp handshake (lane 0 increments once per warp)
    __threadfence();
    __syncwarp();
    int prev = 0;
    if (lane == 0) prev = atomicAdd(&g_rowdone[dst], 1);
    prev = __shfl_sync(0xffffffffu, prev, 0);
    if (prev == 1) {
        __threadfence();
        float4* o4 = (float4*)out;
        const float4* x4 = (const float4*)x;
        size_t base = (size_t)dst * 64 + lane * 2;
        float4 a0 = o4[base], a1 = o4[base + 1];
        float4 r0 = x4[base], r1 = x4[base + 1];
        a0.x += r0.x; a0.y += r0.y; a0.z += r0.z; a0.w += r0.w;
        a1.x += r1.x; a1.y += r1.y; a1.z += r1.z; a1.w += r1.w;
        float s = a0.x + a0.y + a0.z + a0.w + a1.x + a1.y + a1.z + a1.w;
        float q = a0.x * a0.x + a0.y * a0.y + a0.z * a0.z + a0.w * a0.w
                + a1.x * a1.x + a1.y * a1.y + a1.z * a1.z + a1.w * a1.w;
        #pragma unroll
        for (int o = 16; o; o >>= 1) {
            s += __shfl_xor_sync(0xffffffffu, s, o);
            q += __shfl_xor_sync(0xffffffffu, q, o);
        }
        float mu = s * (1.f / 256.f);
        float var = q * (1.f / 256.f) - mu * mu;
        float rs = rsqrtf(var + 1e-5f);
        const float4* g4 = (const float4*)gamma;
        const float4* be4 = (const float4*)beta;
        float4 ga = g4[lane * 2], gb = g4[lane * 2 + 1];
        float4 ba = be4[lane * 2], bb = be4[lane * 2 + 1];
        a0.x = (a0.x - mu) * rs * ga.x + ba.x; a0.y = (a0.y - mu) * rs * ga.y + ba.y;
        a0.z = (a0.z - mu) * rs * ga.z + ba.z; a0.w = (a0.w - mu) * rs * ga.w + ba.w;
        a1.x = (a1.x - mu) * rs * gb.x + bb.x; a1.y = (a1.y - mu) * rs * gb.y + bb.y;
        a1.z = (a1.z - mu) * rs * gb.z + bb.z; a1.w = (a1.w - mu) * rs * gb.w + bb.w;
        o4[base] = a0; o4[base + 1] = a1;
    }
}

// ---------------- launch: fork conv+gemm onto a second stream, overlap with graph prep ----
extern "C" void kernel_launch(void* const* d_in, const int* in_sizes, int n_in,
                              void* d_out, int out_size) {
    const float* x     = (const float*)d_in[0];
    const void*  ei    = d_in[1];
    const float* W0    = (const float*)d_in[2];
    const float* as0   = (const float*)d_in[3];
    const float* ad0   = (const float*)d_in[4];
    const float* b0    = (const float*)d_in[5];
    const float* W1    = (const float*)d_in[6];
    const float* as1   = (const float*)d_in[7];
    const float* ad1   = (const float*)d_in[8];
    const float* b1    = (const float*)d_in[9];
    const float* gamma = (const float*)d_in[10];
    const float* beta  = (const float*)d_in[11];
    float* out = (float*)d_out;

    static cudaStream_t s2 = nullptr;
    static cudaEvent_t evF = nullptr, evJ = nullptr;
    if (s2 == nullptr) {   // infra init on first (non-captured) call; identical work every call
        cudaStreamCreateWithFlags(&s2, cudaStreamNonBlocking);
        cudaEventCreateWithFlags(&evF, cudaEventDisableTiming);
        cudaEventCreateWithFlags(&evJ, cudaEventDisableTiming);
    }

    zero_kernel<<<(NN + 255) / 256, 256>>>((const int*)ei);
    cudaEventRecord(evF, 0);
    cudaStreamWaitEvent(s2, evF, 0);
    // branch A (s2): conversions + GEMM (independent of graph prep)
    conv_w_kernel<<<(256 * 256 + 255) / 256, 256, 0, s2>>>(W0, W1);
    conv_x_kernel<<<(NN * 256 / 8 + 255) / 256, 256, 0, s2>>>(x);
    gemm_mma_kernel<<<dim3(391, 2), 256, 0, s2>>>(as0, ad0, as1, ad1);
    cudaEventRecord(evJ, s2);
    // branch B (legacy): edge prep -> scans -> scatter
    prep_kernel<<<(EE + 255) / 256, 256>>>(ei);
    scan1_kernel<<<dim3(NBLK, 2), 1024>>>();
    scan2_kernel<<<1, 128>>>();
    scan3_kernel<<<dim3(NBLK, 2), 1024>>>();
    scatter_kernel<<<(EE + 255) / 256, 256>>>();
    // join
    cudaStreamWaitEvent(0, evJ, 0);
    agg_kernel<<<(2 * NN + 7) / 8, 256>>>(b0, b1, x, gamma, beta, out);
}

// round 13
// speedup vs baseline: 1.8376x; 1.1686x over previous
#include <cuda_runtime.h>
#include <cuda_bf16.h>
#include <math.h>

#define NN 50000
#define EE 800000
#define NBLK 49
#define CAP 96

// GEMM dynamic smem: 2 buffers x 4 arrays x 10240B + 1KB att
#define GBUF 40960
#define GOFF_AH 0
#define GOFF_AL 10240
#define GOFF_BH 20480
#define GOFF_BL 30720
#define GEMM_SMEM (2 * GBUF + 1024)

// ---------------- scratch (device globals; no allocations allowed) ----------------
__device__ float g_xw[(size_t)NN * 256];          // [N,256]: cols 0..127 hop0, 128..255 hop1
__device__ float g_as0[NN * 8], g_ad0[NN * 8], g_as1[NN * 8], g_ad1[NN * 8];
__device__ int g_src1[EE], g_dst1[EE], g_src2[EE], g_dst2[EE];
__device__ int g_deg1[NN], g_deg2[NN];
__device__ int g_start1[NN + 1], g_start2[NN + 1];
__device__ int g_cur1[NN], g_cur2[NN];
__device__ int g_csr1[EE], g_csr2[EE];
__device__ int g_bsum[2][64], g_boff[2][64];
__device__ int g_rowdone[NN];
__device__ int g_is64;
// bf16 hi/lo splits: x rows [N][256], W as [n=256][k=256] (n = concat out-col)
__device__ uint4 g_xhi4[1601536], g_xlo4[1601536];
__device__ uint4 g_whi4[8192], g_wlo4[8192];

// ---------------- PTX helpers ----------------
__device__ __forceinline__ unsigned smem_to_u32(const void* p) {
    unsigned a;
    asm("{ .reg .u64 t; cvta.to.shared.u64 t, %1; cvt.u32.u64 %0, t; }" : "=r"(a) : "l"(p));
    return a;
}
__device__ __forceinline__ void ldsm_x4(unsigned* r, unsigned addr) {
    asm volatile("ldmatrix.sync.aligned.m8n8.x4.shared.b16 {%0,%1,%2,%3}, [%4];"
        : "=r"(r[0]), "=r"(r[1]), "=r"(r[2]), "=r"(r[3]) : "r"(addr));
}
__device__ __forceinline__ void mma_bf16(float* c, const unsigned* a, unsigned b0, unsigned b1) {
    asm volatile("mma.sync.aligned.m16n8k16.row.col.f32.bf16.bf16.f32 "
        "{%0,%1,%2,%3}, {%4,%5,%6,%7}, {%8,%9}, {%0,%1,%2,%3};"
        : "+f"(c[0]), "+f"(c[1]), "+f"(c[2]), "+f"(c[3])
        : "r"(a[0]), "r"(a[1]), "r"(a[2]), "r"(a[3]), "r"(b0), "r"(b1));
}
__device__ __forceinline__ void cp16(unsigned smaddr, const void* g) {
    asm volatile("cp.async.cg.shared.global [%0], [%1], 16;" :: "r"(smaddr), "l"(g));
}
#define CP_COMMIT() asm volatile("cp.async.commit_group;" ::: "memory")
#define CP_WAIT1()  asm volatile("cp.async.wait_group 1;" ::: "memory")
#define CP_WAIT0()  asm volatile("cp.async.wait_group 0;" ::: "memory")

// ---------------- zero + edge-index dtype detection (fused) ----------------
__global__ void zero_kernel(const int* __restrict__ ei32) {
    int i = blockIdx.x * blockDim.x + threadIdx.x;
    if (i < NN) { g_deg1[i] = 0; g_deg2[i] = 0; g_cur1[i] = 0; g_cur2[i] = 0; g_rowdone[i] = 0; }
    if (blockIdx.x == 0 && threadIdx.x < 32) {
        int v = ei32[2 * threadIdx.x + 1];   // odd words 0 iff int64 (ids < 2^31)
        unsigned b = __ballot_sync(0xffffffffu, v != 0);
        if (threadIdx.x == 0) g_is64 = (b == 0) ? 1 : 0;
    }
}

// ---------------- bf16 hi/lo preconversion ----------------
__global__ void conv_x_kernel(const float* __restrict__ x) {
    int i = blockIdx.x * blockDim.x + threadIdx.x;     // 8 elems per thread
    if (i >= NN * 256 / 8) return;
    const float4* x4 = (const float4*)x;
    float4 a = x4[i * 2], b = x4[i * 2 + 1];
    float v[8] = {a.x, a.y, a.z, a.w, b.x, b.y, b.z, b.w};
    unsigned short hs[8], ls[8];
    #pragma unroll
    for (int j = 0; j < 8; j++) {
        __nv_bfloat16 h = __float2bfloat16(v[j]);
        __nv_bfloat16 l = __float2bfloat16(v[j] - __bfloat162float(h));
        hs[j] = __bfloat16_as_ushort(h);
        ls[j] = __bfloat16_as_ushort(l);
    }
    uint4 uh, ul;
    uh.x = hs[0] | ((unsigned)hs[1] << 16); uh.y = hs[2] | ((unsigned)hs[3] << 16);
    uh.z = hs[4] | ((unsigned)hs[5] << 16); uh.w = hs[6] | ((unsigned)hs[7] << 16);
    ul.x = ls[0] | ((unsigned)ls[1] << 16); ul.y = ls[2] | ((unsigned)ls[3] << 16);
    ul.z = ls[4] | ((unsigned)ls[5] << 16); ul.w = ls[6] | ((unsigned)ls[7] << 16);
    g_xhi4[i] = uh; g_xlo4[i] = ul;
}

__global__ void conv_w_kernel(const float* __restrict__ W0, const float* __restrict__ W1) {
    int idx = blockIdx.x * blockDim.x + threadIdx.x;   // 65536
    if (idx >= 256 * 256) return;
    int n = idx >> 8, k = idx & 255;
    float w = (n < 128) ? W0[k * 128 + n] : W1[k * 128 + (n - 128)];
    __nv_bfloat16 h = __float2bfloat16(w);
    __nv_bfloat16 l = __float2bfloat16(w - __bfloat162float(h));
    ((__nv_bfloat16*)g_whi4)[idx] = h;
    ((__nv_bfloat16*)g_wlo4)[idx] = l;
}

// ---------------- prep: edges + degree counts ----------------
__global__ void prep_kernel(const void* __restrict__ ei) {
    int e = blockIdx.x * blockDim.x + threadIdx.x;
    if (e >= EE) return;
    int s, d, s2, d2;
    if (g_is64) {
        const long long* r = (const long long*)ei;
        s = (int)r[e]; d = (int)r[EE + e];
        s2 = (int)r[d]; d2 = (int)r[EE + d];
    } else {
        const int* r = (const int*)ei;
        s = r[e]; d = r[EE + e];
        s2 = r[d]; d2 = r[EE + d];
    }
    g_src1[e] = s; g_dst1[e] = d;
    g_src2[e] = s2; g_dst2[e] = d2;
    atomicAdd(&g_deg1[d], 1);
    atomicAdd(&g_deg2[d2], 1);
}

// ---------------- 3-stage parallel exclusive scan ----------------
__global__ __launch_bounds__(1024) void scan1_kernel() {
    int arr = blockIdx.y;
    const int* __restrict__ deg = arr ? g_deg2 : g_deg1;
    int* __restrict__ start = arr ? g_start2 : g_start1;
    __shared__ int warpsum[32];
    int t = threadIdx.x, lane = t & 31, w = t >> 5;
    int i = blockIdx.x * 1024 + t;
    int v = (i < NN) ? deg[i] : 0;
    int incl = v;
    #pragma unroll
    for (int o = 1; o < 32; o <<= 1) {
        int u = __shfl_up_sync(0xffffffffu, incl, o);
        if (lane >= o) incl += u;
    }
    if (lane == 31) warpsum[w] = incl;
    __syncthreads();
    if (t < 32) {
        int ws = warpsum[t];
        int wi = ws;
        #pragma unroll
        for (int o = 1; o < 32; o <<= 1) {
            int u = __shfl_up_sync(0xffffffffu, wi, o);
            if (t >= o) wi += u;
        }
        warpsum[t] = wi - ws;
        if (t == 31) g_bsum[arr][blockIdx.x] = wi;
    }
    __syncthreads();
    if (i < NN) start[i] = warpsum[w] + incl - v;
}

__global__ void scan2_kernel() {
    __shared__ int sm[2][64];
    int t = threadIdx.x;
    int arr = t >> 6, i = t & 63;
    int v = (i < NBLK) ? g_bsum[arr][i] : 0;
    sm[arr][i] = v;
    __syncthreads();
    #pragma unroll
    for (int off = 1; off < 64; off <<= 1) {
        int add = (i >= off) ? sm[arr][i - off] : 0;
        __syncthreads();
        sm[arr][i] += add;
        __syncthreads();
    }
    g_boff[arr][i] = sm[arr][i] - v;
    if (i == 63) {
        if (arr == 0) g_start1[NN] = sm[0][63];
        else          g_start2[NN] = sm[1][63];
    }
}

__global__ __launch_bounds__(1024) void scan3_kernel() {
    int arr = blockIdx.y;
    int* __restrict__ start = arr ? g_start2 : g_start1;
    int i = blockIdx.x * 1024 + threadIdx.x;
    if (i < NN) start[i] += g_boff[arr][blockIdx.x];
}

__global__ void scatter_kernel() {
    int e = blockIdx.x * blockDim.x + threadIdx.x;
    if (e >= EE) return;
    {
        int d = g_dst1[e];
        int slot = g_start1[d] + atomicAdd(&g_cur1[d], 1);
        g_csr1[slot] = g_src1[e];
    }
    {
        int d = g_dst2[e];
        int slot = g_start2[d] + atomicAdd(&g_cur2[d], 1);
        g_csr2[slot] = g_src2[e];
    }
}

// ---------------- mma.sync bf16x3 GEMM, cp.async double-buffered, 4x2 warp tiling ----------
// grid (391, 2). Block tile M=128 x N=128, 8 warps as 4(m) x 2(n): warp = 32 rows x 64 cols.
// 64 cols = 4 complete heads -> attention epilogue stays warp-local.
__global__ __launch_bounds__(256) void gemm_mma_kernel(const float* __restrict__ as0,
                                                       const float* __restrict__ ad0,
                                                       const float* __restrict__ as1,
                                                       const float* __restrict__ ad1) {
    extern __shared__ __align__(16) char smc[];
    unsigned sbase = smem_to_u32(smc);
    float* satt_s = (float*)(smc + 2 * GBUF);
    float* satt_d = (float*)(smc + 2 * GBUF + 512);

    int tid = threadIdx.x;
    int w = tid >> 5, lane = tid & 31;
    int wm = w & 3, wn = w >> 2;
    int by = blockIdx.y;
    int rowbase = blockIdx.x * 128;

    {
        const float* __restrict__ avs = by ? as1 : as0;
        const float* __restrict__ avd = by ? ad1 : ad0;
        if (tid < 128) satt_s[tid] = avs[tid];
        else satt_d[tid - 128] = avd[tid - 128];
    }

    float acc[2][8][4];
    #pragma unroll
    for (int mt = 0; mt < 2; mt++)
        #pragma unroll
        for (int j = 0; j < 8; j++)
            #pragma unroll
            for (int q = 0; q < 4; q++) acc[mt][j][q] = 0.f;

    // ldmatrix lane addressing
    int arow0 = wm * 32 + (lane & 15);
    int acolsel = (lane >> 4) << 3;
    int brow = (lane & 7) | ((lane >> 4) << 3);
    int bcolsel = ((lane >> 3) & 1) << 3;

    // issue chunk c into buffer b (each thread: 2 iters x 4 arrays of cp16)
    auto issue = [&](int c, int b) {
        unsigned bb = sbase + b * GBUF;
        char* bc = smc + b * GBUF;
        #pragma unroll
        for (int i = tid; i < 512; i += 256) {
            int r = i >> 2, u = i & 3;
            unsigned so = (unsigned)(r * 80 + u * 16);
            int rowg = rowbase + r;
            if (rowg < NN) {
                cp16(bb + GOFF_AH + so, &g_xhi4[rowg * 32 + c * 4 + u]);
                cp16(bb + GOFF_AL + so, &g_xlo4[rowg * 32 + c * 4 + u]);
            } else {
                *(uint4*)(bc + GOFF_AH + so) = make_uint4(0, 0, 0, 0);
                *(uint4*)(bc + GOFF_AL + so) = make_uint4(0, 0, 0, 0);
            }
            int n = by * 128 + r;
            cp16(bb + GOFF_BH + so, &g_whi4[n * 32 + c * 4 + u]);
            cp16(bb + GOFF_BL + so, &g_wlo4[n * 32 + c * 4 + u]);
        }
    };

    issue(0, 0);
    CP_COMMIT();
    for (int c = 0; c < 8; c++) {
        int b = c & 1;
        if (c < 7) { issue(c + 1, b ^ 1); CP_COMMIT(); CP_WAIT1(); }
        else CP_WAIT0();
        __syncthreads();
        unsigned bb = sbase + b * GBUF;
        #pragma unroll
        for (int ks = 0; ks < 32; ks += 16) {
            unsigned ah[2][4], al[2][4];
            #pragma unroll
            for (int mt = 0; mt < 2; mt++) {
                unsigned aoff = (unsigned)(((arow0 + mt * 16) * 40 + ks + acolsel) * 2);
                ldsm_x4(ah[mt], bb + GOFF_AH + aoff);
                ldsm_x4(al[mt], bb + GOFF_AL + aoff);
            }
            #pragma unroll
            for (int ng = 0; ng < 4; ng++) {
                unsigned bh[4], bl[4];
                unsigned boff = (unsigned)(((wn * 64 + ng * 16 + brow) * 40 + ks + bcolsel) * 2);
                ldsm_x4(bh, bb + GOFF_BH + boff);
                ldsm_x4(bl, bb + GOFF_BL + boff);
                #pragma unroll
                for (int mt = 0; mt < 2; mt++) {
                    mma_bf16(acc[mt][2 * ng],     ah[mt], bh[0], bh[1]);
                    mma_bf16(acc[mt][2 * ng],     ah[mt], bl[0], bl[1]);
                    mma_bf16(acc[mt][2 * ng],     al[mt], bh[0], bh[1]);
                    mma_bf16(acc[mt][2 * ng + 1], ah[mt], bh[2], bh[3]);
                    mma_bf16(acc[mt][2 * ng + 1], ah[mt], bl[2], bl[3]);
                    mma_bf16(acc[mt][2 * ng + 1], al[mt], bh[2], bh[3]);
                }
            }
        }
        __syncthreads();
    }

    // epilogue: rows rowbase + wm*32 + mt*16 + {g, g+8}; cols coff + wn*64 + j*8 + t2
    int g = lane >> 2, t = lane & 3, t2 = t * 2;
    int coff = by * 128 + wn * 64;
    float* __restrict__ gas = by ? g_as1 : g_as0;
    float* __restrict__ gad = by ? g_ad1 : g_ad0;
    #pragma unroll
    for (int mt = 0; mt < 2; mt++) {
        int r0 = rowbase + wm * 32 + mt * 16 + g;
        int r1 = r0 + 8;
        if (r0 < NN) {
            #pragma unroll
            for (int j = 0; j < 8; j++)
                *(float2*)&g_xw[(size_t)r0 * 256 + coff + j * 8 + t2] = make_float2(acc[mt][j][0], acc[mt][j][1]);
        }
        if (r1 < NN) {
            #pragma unroll
            for (int j = 0; j < 8; j++)
                *(float2*)&g_xw[(size_t)r1 * 256 + coff + j * 8 + t2] = make_float2(acc[mt][j][2], acc[mt][j][3]);
        }
        // attention logits for the warp's 4 complete heads
        #pragma unroll
        for (int h2 = 0; h2 < 4; h2++) {
            int h = wn * 4 + h2;
            float vs0 = satt_s[16 * h + t2],     vs1 = satt_s[16 * h + t2 + 1];
            float vs2 = satt_s[16 * h + 8 + t2], vs3 = satt_s[16 * h + 8 + t2 + 1];
            float vd0 = satt_d[16 * h + t2],     vd1 = satt_d[16 * h + t2 + 1];
            float vd2 = satt_d[16 * h + 8 + t2], vd3 = satt_d[16 * h + 8 + t2 + 1];
            float s0 = acc[mt][2*h2][0]*vs0 + acc[mt][2*h2][1]*vs1 + acc[mt][2*h2+1][0]*vs2 + acc[mt][2*h2+1][1]*vs3;
            float d0 = acc[mt][2*h2][0]*vd0 + acc[mt][2*h2][1]*vd1 + acc[mt][2*h2+1][0]*vd2 + acc[mt][2*h2+1][1]*vd3;
            float s1 = acc[mt][2*h2][2]*vs0 + acc[mt][2*h2][3]*vs1 + acc[mt][2*h2+1][2]*vs2 + acc[mt][2*h2+1][3]*vs3;
            float d1 = acc[mt][2*h2][2]*vd0 + acc[mt][2*h2][3]*vd1 + acc[mt][2*h2+1][2]*vd2 + acc[mt][2*h2+1][3]*vd3;
            s0 += __shfl_xor_sync(0xffffffffu, s0, 1); s0 += __shfl_xor_sync(0xffffffffu, s0, 2);
            d0 += __shfl_xor_sync(0xffffffffu, d0, 1); d0 += __shfl_xor_sync(0xffffffffu, d0, 2);
            s1 += __shfl_xor_sync(0xffffffffu, s1, 1); s1 += __shfl_xor_sync(0xffffffffu, s1, 2);
            d1 += __shfl_xor_sync(0xffffffffu, d1, 1); d1 += __shfl_xor_sync(0xffffffffu, d1, 2);
            if (t == 0) {
                if (r0 < NN) { gas[r0 * 8 + h] = s0; gad[r0 * 8 + h] = d0; }
                if (r1 < NN) { gas[r1 * 8 + h] = s1; gad[r1 * 8 + h] = d1; }
            }
        }
    }
}

// ---------------- warp-per-dst softmax+aggregation, smem-cached, fused LN ----------------
__global__ __launch_bounds__(256) void agg_kernel(const float* __restrict__ b0,
                                                  const float* __restrict__ b1,
                                                  const float* __restrict__ x,
                                                  const float* __restrict__ gamma,
                                                  const float* __restrict__ beta,
                                                  float* __restrict__ out) {
    __shared__ int   scache[8][CAP];
    __shared__ float lcache[8][CAP][8];
    int w = threadIdx.x >> 5;
    int gw = blockIdx.x * 8 + w;
    if (gw >= 2 * NN) return;
    int hop = (gw >= NN) ? 1 : 0;
    int dst = gw - hop * NN;
    int lane = threadIdx.x & 31;
    const int* __restrict__ start = hop ? g_start2 : g_start1;
    const int* __restrict__ csr   = hop ? g_csr2 : g_csr1;
    const float* __restrict__ a_s = hop ? g_as1 : g_as0;
    const float* __restrict__ a_d = hop ? g_ad1 : g_ad0;
    const float* __restrict__ bias = hop ? b1 : b0;
    float selfmult = hop ? 2.0f : 1.0f;

    int s0 = start[dst];
    int deg = start[dst + 1] - s0;
    bool cached = (deg <= CAP);

    int h = lane & 7, j = lane >> 3;
    float ad_h = a_d[dst * 8 + h];
    float vself = a_s[dst * 8 + h] + ad_h;
    vself = vself > 0.f ? vself : 0.2f * vself;
    float m = (j == 0) ? vself : -1e30f;
    float sum = (j == 0) ? selfmult : 0.f;

    if (cached) {
        for (int e = lane; e < deg; e += 32) scache[w][e] = csr[s0 + e];
        __syncwarp();
        for (int e = j; e < deg; e += 4) {
            int src = scache[w][e];
            float v = a_s[src * 8 + h] + ad_h;
            v = v > 0.f ? v : 0.2f * v;
            lcache[w][e][h] = v;
            float nm = fmaxf(m, v);
            sum = sum * __expf(m - nm) + __expf(v - nm);
            m = nm;
        }
        __syncwarp();
    } else {
        for (int e = j; e < deg; e += 4) {
            int src = csr[s0 + e];
            float v = a_s[src * 8 + h] + ad_h;
            v = v > 0.f ? v : 0.2f * v;
            float nm = fmaxf(m, v);
            sum = sum * __expf(m - nm) + __expf(v - nm);
            m = nm;
        }
    }
    #pragma unroll
    for (int o = 8; o <= 16; o <<= 1) {
        float om = __shfl_xor_sync(0xffffffffu, m, o);
        float os = __shfl_xor_sync(0xffffffffu, sum, o);
        float nm = fmaxf(m, om);
        sum = sum * __expf(m - nm) + os * __expf(om - nm);
        m = nm;
    }

    int hh = lane >> 2;
    float mh = __shfl_sync(0xffffffffu, m, hh);
    float is = 1.f / __shfl_sync(0xffffffffu, sum, hh);
    float adh = __shfl_sync(0xffffffffu, ad_h, hh);
    int off4 = hop ? 32 : 0;
    const float4* __restrict__ xw4 = (const float4*)g_xw;
    float4 acc = make_float4(0.f, 0.f, 0.f, 0.f);

    if (cached) {
        int e = 0;
        for (; e + 4 <= deg; e += 4) {
            int sA = scache[w][e],     sB = scache[w][e + 1];
            int sC = scache[w][e + 2], sD = scache[w][e + 3];
            float vA = lcache[w][e][hh],     vB = lcache[w][e + 1][hh];
            float vC = lcache[w][e + 2][hh], vD = lcache[w][e + 3][hh];
            float4 fA = xw4[(size_t)sA * 64 + off4 + lane];
            float4 fB = xw4[(size_t)sB * 64 + off4 + lane];
            float4 fC = xw4[(size_t)sC * 64 + off4 + lane];
            float4 fD = xw4[(size_t)sD * 64 + off4 + lane];
            float aA = __expf(vA - mh) * is, aB = __expf(vB - mh) * is;
            float aC = __expf(vC - mh) * is, aD = __expf(vD - mh) * is;
            acc.x += aA * fA.x; acc.y += aA * fA.y; acc.z += aA * fA.z; acc.w += aA * fA.w;
            acc.x += aB * fB.x; acc.y += aB * fB.y; acc.z += aB * fB.z; acc.w += aB * fB.w;
            acc.x += aC * fC.x; acc.y += aC * fC.y; acc.z += aC * fC.z; acc.w += aC * fC.w;
            acc.x += aD * fD.x; acc.y += aD * fD.y; acc.z += aD * fD.z; acc.w += aD * fD.w;
        }
        for (; e < deg; e++) {
            int src = scache[w][e];
            float v = lcache[w][e][hh];
            float al = __expf(v - mh) * is;
            float4 f = xw4[(size_t)src * 64 + off4 + lane];
            acc.x += al * f.x; acc.y += al * f.y; acc.z += al * f.z; acc.w += al * f.w;
        }
    } else {
        #pragma unroll 2
        for (int e = 0; e < deg; e++) {
            int src = csr[s0 + e];
            float v = a_s[src * 8 + hh] + adh;
            v = v > 0.f ? v : 0.2f * v;
            float al = __expf(v - mh) * is;
            float4 f = xw4[(size_t)src * 64 + off4 + lane];
            acc.x += al * f.x; acc.y += al * f.y; acc.z += al * f.z; acc.w += al * f.w;
        }
    }
    {   // self-loop term
        float v = a_s[dst * 8 + hh] + adh;
        v = v > 0.f ? v : 0.2f * v;
        float al = selfmult * __expf(v - mh) * is;
        float4 f = xw4[(size_t)dst * 64 + off4 + lane];
        acc.x += al * f.x; acc.y += al * f.y; acc.z += al * f.z; acc.w += al * f.w;
    }
    float4 bv = ((const float4*)bias)[lane];
    acc.x += bv.x; acc.y += bv.y; acc.z += bv.z; acc.w += bv.w;
    ((float4*)out)[(size_t)dst * 64 + off4 + lane] = acc;

    // fused residual + LayerNorm: per-warp handshake (lane 0 increments once per warp)
    __threadfence();
    __syncwarp();
    int prev = 0;
    if (lane == 0) prev = atomicAdd(&g_rowdone[dst], 1);
    prev = __shfl_sync(0xffffffffu, prev, 0);
    if (prev == 1) {
        __threadfence();
        float4* o4 = (float4*)out;
        const float4* x4 = (const float4*)x;
        size_t base = (size_t)dst * 64 + lane * 2;
        float4 a0 = o4[base], a1 = o4[base + 1];
        float4 r0 = x4[base], r1 = x4[base + 1];
        a0.x += r0.x; a0.y += r0.y; a0.z += r0.z; a0.w += r0.w;
        a1.x += r1.x; a1.y += r1.y; a1.z += r1.z; a1.w += r1.w;
        float s = a0.x + a0.y + a0.z + a0.w + a1.x + a1.y + a1.z + a1.w;
        float q = a0.x * a0.x + a0.y * a0.y + a0.z * a0.z + a0.w * a0.w
                + a1.x * a1.x + a1.y * a1.y + a1.z * a1.z + a1.w * a1.w;
        #pragma unroll
        for (int o = 16; o; o >>= 1) {
            s += __shfl_xor_sync(0xffffffffu, s, o);
            q += __shfl_xor_sync(0xffffffffu, q, o);
        }
        float mu = s * (1.f / 256.f);
        float var = q * (1.f / 256.f) - mu * mu;
        float rs = rsqrtf(var + 1e-5f);
        const float4* g4 = (const float4*)gamma;
        const float4* be4 = (const float4*)beta;
        float4 ga = g4[lane * 2], gb = g4[lane * 2 + 1];
        float4 ba = be4[lane * 2], bb = be4[lane * 2 + 1];
        a0.x = (a0.x - mu) * rs * ga.x + ba.x; a0.y = (a0.y - mu) * rs * ga.y + ba.y;
        a0.z = (a0.z - mu) * rs * ga.z + ba.z; a0.w = (a0.w - mu) * rs * ga.w + ba.w;
        a1.x = (a1.x - mu) * rs * gb.x + bb.x; a1.y = (a1.y - mu) * rs * gb.y + bb.y;
        a1.z = (a1.z - mu) * rs * gb.z + bb.z; a1.w = (a1.w - mu) * rs * gb.w + bb.w;
        o4[base] = a0; o4[base + 1] = a1;
    }
}

// ---------------- launch: fork conv+gemm onto a second stream, overlap with graph prep ----
extern "C" void kernel_launch(void* const* d_in, const int* in_sizes, int n_in,
                              void* d_out, int out_size) {
    const float* x     = (const float*)d_in[0];
    const void*  ei    = d_in[1];
    const float* W0    = (const float*)d_in[2];
    const float* as0   = (const float*)d_in[3];
    const float* ad0   = (const float*)d_in[4];
    const float* b0    = (const float*)d_in[5];
    const float* W1    = (const float*)d_in[6];
    const float* as1   = (const float*)d_in[7];
    const float* ad1   = (const float*)d_in[8];
    const float* b1    = (const float*)d_in[9];
    const float* gamma = (const float*)d_in[10];
    const float* beta  = (const float*)d_in[11];
    float* out = (float*)d_out;

    static cudaStream_t s2 = nullptr;
    static cudaEvent_t evF = nullptr, evJ = nullptr;
    if (s2 == nullptr) {   // infra init on first (non-captured) call; identical work every call
        cudaStreamCreateWithFlags(&s2, cudaStreamNonBlocking);
        cudaEventCreateWithFlags(&evF, cudaEventDisableTiming);
        cudaEventCreateWithFlags(&evJ, cudaEventDisableTiming);
        cudaFuncSetAttribute(gemm_mma_kernel, cudaFuncAttributeMaxDynamicSharedMemorySize, GEMM_SMEM);
    }

    zero_kernel<<<(NN + 255) / 256, 256>>>((const int*)ei);
    cudaEventRecord(evF, 0);
    cudaStreamWaitEvent(s2, evF, 0);
    // branch A (s2): conversions + GEMM (independent of graph prep)
    conv_w_kernel<<<(256 * 256 + 255) / 256, 256, 0, s2>>>(W0, W1);
    conv_x_kernel<<<(NN * 256 / 8 + 255) / 256, 256, 0, s2>>>(x);
    gemm_mma_kernel<<<dim3(391, 2), 256, GEMM_SMEM, s2>>>(as0, ad0, as1, ad1);
    cudaEventRecord(evJ, s2);
    // branch B (legacy): edge prep -> scans -> scatter
    prep_kernel<<<(EE + 255) / 256, 256>>>(ei);
    scan1_kernel<<<dim3(NBLK, 2), 1024>>>();
    scan2_kernel<<<1, 128>>>();
    scan3_kernel<<<dim3(NBLK, 2), 1024>>>();
    scatter_kernel<<<(EE + 255) / 256, 256>>>();
    // join
    cudaStreamWaitEvent(0, evJ, 0);
    agg_kernel<<<(2 * NN + 7) / 8, 256>>>(b0, b1, x, gamma, beta, out);
}

// round 14
// speedup vs baseline: 2.0017x; 1.0893x over previous
#include <cuda_runtime.h>
#include <cuda_bf16.h>
#include <math.h>

#define NN 50000
#define EE 800000
#define NBLK 49
#define CAP 80

// GEMM dynamic smem: 2 buffers x 4 arrays x 10240B + 1KB att
#define GBUF 40960
#define GOFF_AH 0
#define GOFF_AL 10240
#define GOFF_BH 20480
#define GOFF_BL 30720
#define GEMM_SMEM (2 * GBUF + 1024)

// ---------------- scratch (device globals; no allocations allowed) ----------------
__device__ float g_xw[(size_t)NN * 256];          // [N,256]: cols 0..127 hop0, 128..255 hop1
__device__ float g_as0[NN * 8], g_ad0[NN * 8], g_as1[NN * 8], g_ad1[NN * 8];
__device__ int g_src1[EE], g_dst1[EE], g_src2[EE], g_dst2[EE];
__device__ int g_deg1[NN], g_deg2[NN];
__device__ int g_start1[NN + 1], g_start2[NN + 1];
__device__ int g_cur1[NN], g_cur2[NN];
__device__ int g_csr1[EE], g_csr2[EE];
__device__ int g_bsum[2][64], g_boff[2][64];
__device__ int g_is64;
// bf16 hi/lo splits: x rows [N][256], W as [n=256][k=256] (n = concat out-col)
__device__ uint4 g_xhi4[1601536], g_xlo4[1601536];
__device__ uint4 g_whi4[8192], g_wlo4[8192];

// ---------------- PTX helpers ----------------
__device__ __forceinline__ unsigned smem_to_u32(const void* p) {
    unsigned a;
    asm("{ .reg .u64 t; cvta.to.shared.u64 t, %1; cvt.u32.u64 %0, t; }" : "=r"(a) : "l"(p));
    return a;
}
__device__ __forceinline__ void ldsm_x4(unsigned* r, unsigned addr) {
    asm volatile("ldmatrix.sync.aligned.m8n8.x4.shared.b16 {%0,%1,%2,%3}, [%4];"
        : "=r"(r[0]), "=r"(r[1]), "=r"(r[2]), "=r"(r[3]) : "r"(addr));
}
__device__ __forceinline__ void mma_bf16(float* c, const unsigned* a, unsigned b0, unsigned b1) {
    asm volatile("mma.sync.aligned.m16n8k16.row.col.f32.bf16.bf16.f32 "
        "{%0,%1,%2,%3}, {%4,%5,%6,%7}, {%8,%9}, {%0,%1,%2,%3};"
        : "+f"(c[0]), "+f"(c[1]), "+f"(c[2]), "+f"(c[3])
        : "r"(a[0]), "r"(a[1]), "r"(a[2]), "r"(a[3]), "r"(b0), "r"(b1));
}
__device__ __forceinline__ void cp16(unsigned smaddr, const void* g) {
    asm volatile("cp.async.cg.shared.global [%0], [%1], 16;" :: "r"(smaddr), "l"(g));
}
#define CP_COMMIT() asm volatile("cp.async.commit_group;" ::: "memory")
#define CP_WAIT1()  asm volatile("cp.async.wait_group 1;" ::: "memory")
#define CP_WAIT0()  asm volatile("cp.async.wait_group 0;" ::: "memory")

// ---------------- zero + edge-index dtype detection (fused) ----------------
__global__ void zero_kernel(const int* __restrict__ ei32) {
    int i = blockIdx.x * blockDim.x + threadIdx.x;
    if (i < NN) { g_deg1[i] = 0; g_deg2[i] = 0; g_cur1[i] = 0; g_cur2[i] = 0; }
    if (blockIdx.x == 0 && threadIdx.x < 32) {
        int v = ei32[2 * threadIdx.x + 1];   // odd words 0 iff int64 (ids < 2^31)
        unsigned b = __ballot_sync(0xffffffffu, v != 0);
        if (threadIdx.x == 0) g_is64 = (b == 0) ? 1 : 0;
    }
}

// ---------------- bf16 hi/lo preconversion ----------------
__global__ void conv_x_kernel(const float* __restrict__ x) {
    int i = blockIdx.x * blockDim.x + threadIdx.x;     // 8 elems per thread
    if (i >= NN * 256 / 8) return;
    const float4* x4 = (const float4*)x;
    float4 a = x4[i * 2], b = x4[i * 2 + 1];
    float v[8] = {a.x, a.y, a.z, a.w, b.x, b.y, b.z, b.w};
    unsigned short hs[8], ls[8];
    #pragma unroll
    for (int j = 0; j < 8; j++) {
        __nv_bfloat16 h = __float2bfloat16(v[j]);
        __nv_bfloat16 l = __float2bfloat16(v[j] - __bfloat162float(h));
        hs[j] = __bfloat16_as_ushort(h);
        ls[j] = __bfloat16_as_ushort(l);
    }
    uint4 uh, ul;
    uh.x = hs[0] | ((unsigned)hs[1] << 16); uh.y = hs[2] | ((unsigned)hs[3] << 16);
    uh.z = hs[4] | ((unsigned)hs[5] << 16); uh.w = hs[6] | ((unsigned)hs[7] << 16);
    ul.x = ls[0] | ((unsigned)ls[1] << 16); ul.y = ls[2] | ((unsigned)ls[3] << 16);
    ul.z = ls[4] | ((unsigned)ls[5] << 16); ul.w = ls[6] | ((unsigned)ls[7] << 16);
    g_xhi4[i] = uh; g_xlo4[i] = ul;
}

__global__ void conv_w_kernel(const float* __restrict__ W0, const float* __restrict__ W1) {
    int idx = blockIdx.x * blockDim.x + threadIdx.x;   // 65536
    if (idx >= 256 * 256) return;
    int n = idx >> 8, k = idx & 255;
    float w = (n < 128) ? W0[k * 128 + n] : W1[k * 128 + (n - 128)];
    __nv_bfloat16 h = __float2bfloat16(w);
    __nv_bfloat16 l = __float2bfloat16(w - __bfloat162float(h));
    ((__nv_bfloat16*)g_whi4)[idx] = h;
    ((__nv_bfloat16*)g_wlo4)[idx] = l;
}

// ---------------- prep: edges + degree counts ----------------
__global__ void prep_kernel(const void* __restrict__ ei) {
    int e = blockIdx.x * blockDim.x + threadIdx.x;
    if (e >= EE) return;
    int s, d, s2, d2;
    if (g_is64) {
        const long long* r = (const long long*)ei;
        s = (int)r[e]; d = (int)r[EE + e];
        s2 = (int)r[d]; d2 = (int)r[EE + d];
    } else {
        const int* r = (const int*)ei;
        s = r[e]; d = r[EE + e];
        s2 = r[d]; d2 = r[EE + d];
    }
    g_src1[e] = s; g_dst1[e] = d;
    g_src2[e] = s2; g_dst2[e] = d2;
    atomicAdd(&g_deg1[d], 1);
    atomicAdd(&g_deg2[d2], 1);
}

// ---------------- 3-stage parallel exclusive scan ----------------
__global__ __launch_bounds__(1024) void scan1_kernel() {
    int arr = blockIdx.y;
    const int* __restrict__ deg = arr ? g_deg2 : g_deg1;
    int* __restrict__ start = arr ? g_start2 : g_start1;
    __shared__ int warpsum[32];
    int t = threadIdx.x, lane = t & 31, w = t >> 5;
    int i = blockIdx.x * 1024 + t;
    int v = (i < NN) ? deg[i] : 0;
    int incl = v;
    #pragma unroll
    for (int o = 1; o < 32; o <<= 1) {
        int u = __shfl_up_sync(0xffffffffu, incl, o);
        if (lane >= o) incl += u;
    }
    if (lane == 31) warpsum[w] = incl;
    __syncthreads();
    if (t < 32) {
        int ws = warpsum[t];
        int wi = ws;
        #pragma unroll
        for (int o = 1; o < 32; o <<= 1) {
            int u = __shfl_up_sync(0xffffffffu, wi, o);
            if (t >= o) wi += u;
        }
        warpsum[t] = wi - ws;
        if (t == 31) g_bsum[arr][blockIdx.x] = wi;
    }
    __syncthreads();
    if (i < NN) start[i] = warpsum[w] + incl - v;
}

__global__ void scan2_kernel() {
    __shared__ int sm[2][64];
    int t = threadIdx.x;
    int arr = t >> 6, i = t & 63;
    int v = (i < NBLK) ? g_bsum[arr][i] : 0;
    sm[arr][i] = v;
    __syncthreads();
    #pragma unroll
    for (int off = 1; off < 64; off <<= 1) {
        int add = (i >= off) ? sm[arr][i - off] : 0;
        __syncthreads();
        sm[arr][i] += add;
        __syncthreads();
    }
    g_boff[arr][i] = sm[arr][i] - v;
    if (i == 63) {
        if (arr == 0) g_start1[NN] = sm[0][63];
        else          g_start2[NN] = sm[1][63];
    }
}

__global__ __launch_bounds__(1024) void scan3_kernel() {
    int arr = blockIdx.y;
    int* __restrict__ start = arr ? g_start2 : g_start1;
    int i = blockIdx.x * 1024 + threadIdx.x;
    if (i < NN) start[i] += g_boff[arr][blockIdx.x];
}

__global__ void scatter_kernel() {
    int e = blockIdx.x * blockDim.x + threadIdx.x;
    if (e >= EE) return;
    {
        int d = g_dst1[e];
        int slot = g_start1[d] + atomicAdd(&g_cur1[d], 1);
        g_csr1[slot] = g_src1[e];
    }
    {
        int d = g_dst2[e];
        int slot = g_start2[d] + atomicAdd(&g_cur2[d], 1);
        g_csr2[slot] = g_src2[e];
    }
}

// ---------------- mma.sync bf16x3 GEMM, cp.async double-buffered, 4x2 warp tiling ----------
__global__ __launch_bounds__(256) void gemm_mma_kernel(const float* __restrict__ as0,
                                                       const float* __restrict__ ad0,
                                                       const float* __restrict__ as1,
                                                       const float* __restrict__ ad1) {
    extern __shared__ __align__(16) char smc[];
    unsigned sbase = smem_to_u32(smc);
    float* satt_s = (float*)(smc + 2 * GBUF);
    float* satt_d = (float*)(smc + 2 * GBUF + 512);

    int tid = threadIdx.x;
    int w = tid >> 5, lane = tid & 31;
    int wm = w & 3, wn = w >> 2;
    int by = blockIdx.y;
    int rowbase = blockIdx.x * 128;

    {
        const float* __restrict__ avs = by ? as1 : as0;
        const float* __restrict__ avd = by ? ad1 : ad0;
        if (tid < 128) satt_s[tid] = avs[tid];
        else satt_d[tid - 128] = avd[tid - 128];
    }

    float acc[2][8][4];
    #pragma unroll
    for (int mt = 0; mt < 2; mt++)
        #pragma unroll
        for (int j = 0; j < 8; j++)
            #pragma unroll
            for (int q = 0; q < 4; q++) acc[mt][j][q] = 0.f;

    int arow0 = wm * 32 + (lane & 15);
    int acolsel = (lane >> 4) << 3;
    int brow = (lane & 7) | ((lane >> 4) << 3);
    int bcolsel = ((lane >> 3) & 1) << 3;

    auto issue = [&](int c, int b) {
        unsigned bb = sbase + b * GBUF;
        char* bc = smc + b * GBUF;
        #pragma unroll
        for (int i = tid; i < 512; i += 256) {
            int r = i >> 2, u = i & 3;
            unsigned so = (unsigned)(r * 80 + u * 16);
            int rowg = rowbase + r;
            if (rowg < NN) {
                cp16(bb + GOFF_AH + so, &g_xhi4[rowg * 32 + c * 4 + u]);
                cp16(bb + GOFF_AL + so, &g_xlo4[rowg * 32 + c * 4 + u]);
            } else {
                *(uint4*)(bc + GOFF_AH + so) = make_uint4(0, 0, 0, 0);
                *(uint4*)(bc + GOFF_AL + so) = make_uint4(0, 0, 0, 0);
            }
            int n = by * 128 + r;
            cp16(bb + GOFF_BH + so, &g_whi4[n * 32 + c * 4 + u]);
            cp16(bb + GOFF_BL + so, &g_wlo4[n * 32 + c * 4 + u]);
        }
    };

    issue(0, 0);
    CP_COMMIT();
    for (int c = 0; c < 8; c++) {
        int b = c & 1;
        if (c < 7) { issue(c + 1, b ^ 1); CP_COMMIT(); CP_WAIT1(); }
        else CP_WAIT0();
        __syncthreads();
        unsigned bb = sbase + b * GBUF;
        #pragma unroll
        for (int ks = 0; ks < 32; ks += 16) {
            unsigned ah[2][4], al[2][4];
            #pragma unroll
            for (int mt = 0; mt < 2; mt++) {
                unsigned aoff = (unsigned)(((arow0 + mt * 16) * 40 + ks + acolsel) * 2);
                ldsm_x4(ah[mt], bb + GOFF_AH + aoff);
                ldsm_x4(al[mt], bb + GOFF_AL + aoff);
            }
            #pragma unroll
            for (int ng = 0; ng < 4; ng++) {
                unsigned bh[4], bl[4];
                unsigned boff = (unsigned)(((wn * 64 + ng * 16 + brow) * 40 + ks + bcolsel) * 2);
                ldsm_x4(bh, bb + GOFF_BH + boff);
                ldsm_x4(bl, bb + GOFF_BL + boff);
                #pragma unroll
                for (int mt = 0; mt < 2; mt++) {
                    mma_bf16(acc[mt][2 * ng],     ah[mt], bh[0], bh[1]);
                    mma_bf16(acc[mt][2 * ng],     ah[mt], bl[0], bl[1]);
                    mma_bf16(acc[mt][2 * ng],     al[mt], bh[0], bh[1]);
                    mma_bf16(acc[mt][2 * ng + 1], ah[mt], bh[2], bh[3]);
                    mma_bf16(acc[mt][2 * ng + 1], ah[mt], bl[2], bl[3]);
                    mma_bf16(acc[mt][2 * ng + 1], al[mt], bh[2], bh[3]);
                }
            }
        }
        __syncthreads();
    }

    int g = lane >> 2, t = lane & 3, t2 = t * 2;
    int coff = by * 128 + wn * 64;
    float* __restrict__ gas = by ? g_as1 : g_as0;
    float* __restrict__ gad = by ? g_ad1 : g_ad0;
    #pragma unroll
    for (int mt = 0; mt < 2; mt++) {
        int r0 = rowbase + wm * 32 + mt * 16 + g;
        int r1 = r0 + 8;
        if (r0 < NN) {
            #pragma unroll
            for (int j = 0; j < 8; j++)
                *(float2*)&g_xw[(size_t)r0 * 256 + coff + j * 8 + t2] = make_float2(acc[mt][j][0], acc[mt][j][1]);
        }
        if (r1 < NN) {
            #pragma unroll
            for (int j = 0; j < 8; j++)
                *(float2*)&g_xw[(size_t)r1 * 256 + coff + j * 8 + t2] = make_float2(acc[mt][j][2], acc[mt][j][3]);
        }
        #pragma unroll
        for (int h2 = 0; h2 < 4; h2++) {
            int h = wn * 4 + h2;
            float vs0 = satt_s[16 * h + t2],     vs1 = satt_s[16 * h + t2 + 1];
            float vs2 = satt_s[16 * h + 8 + t2], vs3 = satt_s[16 * h + 8 + t2 + 1];
            float vd0 = satt_d[16 * h + t2],     vd1 = satt_d[16 * h + t2 + 1];
            float vd2 = satt_d[16 * h + 8 + t2], vd3 = satt_d[16 * h + 8 + t2 + 1];
            float s0 = acc[mt][2*h2][0]*vs0 + acc[mt][2*h2][1]*vs1 + acc[mt][2*h2+1][0]*vs2 + acc[mt][2*h2+1][1]*vs3;
            float d0 = acc[mt][2*h2][0]*vd0 + acc[mt][2*h2][1]*vd1 + acc[mt][2*h2+1][0]*vd2 + acc[mt][2*h2+1][1]*vd3;
            float s1 = acc[mt][2*h2][2]*vs0 + acc[mt][2*h2][3]*vs1 + acc[mt][2*h2+1][2]*vs2 + acc[mt][2*h2+1][3]*vs3;
            float d1 = acc[mt][2*h2][2]*vd0 + acc[mt][2*h2][3]*vd1 + acc[mt][2*h2+1][2]*vd2 + acc[mt][2*h2+1][3]*vd3;
            s0 += __shfl_xor_sync(0xffffffffu, s0, 1); s0 += __shfl_xor_sync(0xffffffffu, s0, 2);
            d0 += __shfl_xor_sync(0xffffffffu, d0, 1); d0 += __shfl_xor_sync(0xffffffffu, d0, 2);
            s1 += __shfl_xor_sync(0xffffffffu, s1, 1); s1 += __shfl_xor_sync(0xffffffffu, s1, 2);
            d1 += __shfl_xor_sync(0xffffffffu, d1, 1); d1 += __shfl_xor_sync(0xffffffffu, d1, 2);
            if (t == 0) {
                if (r0 < NN) { gas[r0 * 8 + h] = s0; gad[r0 * 8 + h] = d0; }
                if (r1 < NN) { gas[r1 * 8 + h] = s1; gad[r1 * 8 + h] = d1; }
            }
        }
    }
}

// ---------------- warp-per-DST (both hops) softmax+agg + in-register residual+LN ----------
// 8 warps/block, one dst per warp. Warp does hop0 then hop1 aggregation (halves in regs),
// then LayerNorm entirely in registers: no atomics, no fences, single write of final row.
// selfmult: hop2 = 2 (reference double-appends self loops on hop 2).
__global__ __launch_bounds__(256) void agg_kernel(const float* __restrict__ b0,
                                                  const float* __restrict__ b1,
                                                  const float* __restrict__ x,
                                                  const float* __restrict__ gamma,
                                                  const float* __restrict__ beta,
                                                  float* __restrict__ out) {
    __shared__ int   scache[8][2][CAP];
    __shared__ float lcache[8][2][CAP][8];
    int w = threadIdx.x >> 5;
    int dst = blockIdx.x * 8 + w;
    if (dst >= NN) return;
    int lane = threadIdx.x & 31;
    int h = lane & 7, j = lane >> 3;
    int hh = lane >> 2;
    const float4* __restrict__ xw4 = (const float4*)g_xw;

    float4 accH[2];
    float mhH[2], isH[2];

    #pragma unroll
    for (int hop = 0; hop < 2; hop++) {
        const int* __restrict__ start = hop ? g_start2 : g_start1;
        const int* __restrict__ csr   = hop ? g_csr2 : g_csr1;
        const float* __restrict__ a_s = hop ? g_as1 : g_as0;
        const float* __restrict__ a_d = hop ? g_ad1 : g_ad0;
        float selfmult = hop ? 2.0f : 1.0f;
        int s0 = start[dst];
        int deg = start[dst + 1] - s0;
        bool cached = (deg <= CAP);

        // pass 1: online softmax; lane = h + 8*j; self-loop in j==0 init
        float ad_h = a_d[dst * 8 + h];
        float vself = a_s[dst * 8 + h] + ad_h;
        vself = vself > 0.f ? vself : 0.2f * vself;
        float m = (j == 0) ? vself : -1e30f;
        float sum = (j == 0) ? selfmult : 0.f;
        if (cached) {
            for (int e = lane; e < deg; e += 32) scache[w][hop][e] = csr[s0 + e];
            __syncwarp();
            for (int e = j; e < deg; e += 4) {
                int src = scache[w][hop][e];
                float v = a_s[src * 8 + h] + ad_h;
                v = v > 0.f ? v : 0.2f * v;
                lcache[w][hop][e][h] = v;
                float nm = fmaxf(m, v);
                sum = sum * __expf(m - nm) + __expf(v - nm);
                m = nm;
            }
            __syncwarp();
        } else {
            for (int e = j; e < deg; e += 4) {
                int src = csr[s0 + e];
                float v = a_s[src * 8 + h] + ad_h;
                v = v > 0.f ? v : 0.2f * v;
                float nm = fmaxf(m, v);
                sum = sum * __expf(m - nm) + __expf(v - nm);
                m = nm;
            }
        }
        #pragma unroll
        for (int o = 8; o <= 16; o <<= 1) {
            float om = __shfl_xor_sync(0xffffffffu, m, o);
            float os = __shfl_xor_sync(0xffffffffu, sum, o);
            float nm = fmaxf(m, om);
            sum = sum * __expf(m - nm) + os * __expf(om - nm);
            m = nm;
        }
        float mh = __shfl_sync(0xffffffffu, m, hh);
        float is = 1.f / __shfl_sync(0xffffffffu, sum, hh);
        float adh = __shfl_sync(0xffffffffu, ad_h, hh);
        mhH[hop] = mh; isH[hop] = is;

        // pass 2: lane owns 4 channels of this hop's 128; batch-8 independent gathers
        int off4 = hop ? 32 : 0;
        float4 acc = make_float4(0.f, 0.f, 0.f, 0.f);
        if (cached) {
            int e = 0;
            for (; e + 8 <= deg; e += 8) {
                int   sv[8];
                float lv[8];
                float4 fv[8];
                #pragma unroll
                for (int q = 0; q < 8; q++) {
                    sv[q] = scache[w][hop][e + q];
                    lv[q] = lcache[w][hop][e + q][hh];
                }
                #pragma unroll
                for (int q = 0; q < 8; q++)
                    fv[q] = xw4[(size_t)sv[q] * 64 + off4 + lane];
                #pragma unroll
                for (int q = 0; q < 8; q++) {
                    float al = __expf(lv[q] - mh) * is;
                    acc.x += al * fv[q].x; acc.y += al * fv[q].y;
                    acc.z += al * fv[q].z; acc.w += al * fv[q].w;
                }
            }
            for (; e < deg; e++) {
                int src = scache[w][hop][e];
                float al = __expf(lcache[w][hop][e][hh] - mh) * is;
                float4 f = xw4[(size_t)src * 64 + off4 + lane];
                acc.x += al * f.x; acc.y += al * f.y; acc.z += al * f.z; acc.w += al * f.w;
            }
        } else {
            #pragma unroll 2
            for (int e = 0; e < deg; e++) {
                int src = csr[s0 + e];
                float v = a_s[src * 8 + hh] + adh;
                v = v > 0.f ? v : 0.2f * v;
                float al = __expf(v - mh) * is;
                float4 f = xw4[(size_t)src * 64 + off4 + lane];
                acc.x += al * f.x; acc.y += al * f.y; acc.z += al * f.z; acc.w += al * f.w;
            }
        }
        {   // self-loop term
            float v = a_s[dst * 8 + hh] + adh;
            v = v > 0.f ? v : 0.2f * v;
            float al = selfmult * __expf(v - mh) * is;
            float4 f = xw4[(size_t)dst * 64 + off4 + lane];
            acc.x += al * f.x; acc.y += al * f.y; acc.z += al * f.z; acc.w += al * f.w;
        }
        const float* __restrict__ bias = hop ? b1 : b0;
        float4 bv = ((const float4*)bias)[lane];
        acc.x += bv.x; acc.y += bv.y; acc.z += bv.z; acc.w += bv.w;
        accH[hop] = acc;
    }

    // residual + LayerNorm in registers: lane holds chans [lane*4, +4) and [128+lane*4, +4)
    const float4* __restrict__ x4 = (const float4*)x;
    size_t base = (size_t)dst * 64 + lane;
    float4 a0 = accH[0], a1 = accH[1];
    float4 r0 = x4[base], r1 = x4[base + 32];
    a0.x += r0.x; a0.y += r0.y; a0.z += r0.z; a0.w += r0.w;
    a1.x += r1.x; a1.y += r1.y; a1.z += r1.z; a1.w += r1.w;
    float s = a0.x + a0.y + a0.z + a0.w + a1.x + a1.y + a1.z + a1.w;
    float q = a0.x * a0.x + a0.y * a0.y + a0.z * a0.z + a0.w * a0.w
            + a1.x * a1.x + a1.y * a1.y + a1.z * a1.z + a1.w * a1.w;
    #pragma unroll
    for (int o = 16; o; o >>= 1) {
        s += __shfl_xor_sync(0xffffffffu, s, o);
        q += __shfl_xor_sync(0xffffffffu, q, o);
    }
    float mu = s * (1.f / 256.f);
    float var = q * (1.f / 256.f) - mu * mu;
    float rs = rsqrtf(var + 1e-5f);
    const float4* g4 = (const float4*)gamma;
    const float4* be4 = (const float4*)beta;
    float4 ga = g4[lane], gb = g4[lane + 32];
    float4 ba = be4[lane], bb = be4[lane + 32];
    a0.x = (a0.x - mu) * rs * ga.x + ba.x; a0.y = (a0.y - mu) * rs * ga.y + ba.y;
    a0.z = (a0.z - mu) * rs * ga.z + ba.z; a0.w = (a0.w - mu) * rs * ga.w + ba.w;
    a1.x = (a1.x - mu) * rs * gb.x + bb.x; a1.y = (a1.y - mu) * rs * gb.y + bb.y;
    a1.z = (a1.z - mu) * rs * gb.z + bb.z; a1.w = (a1.w - mu) * rs * gb.w + bb.w;
    float4* o4 = (float4*)out;
    o4[base] = a0;
    o4[base + 32] = a1;
}

// ---------------- launch: fork conv+gemm onto a second stream, overlap with graph prep ----
extern "C" void kernel_launch(void* const* d_in, const int* in_sizes, int n_in,
                              void* d_out, int out_size) {
    const float* x     = (const float*)d_in[0];
    const void*  ei    = d_in[1];
    const float* W0    = (const float*)d_in[2];
    const float* as0   = (const float*)d_in[3];
    const float* ad0   = (const float*)d_in[4];
    const float* b0    = (const float*)d_in[5];
    const float* W1    = (const float*)d_in[6];
    const float* as1   = (const float*)d_in[7];
    const float* ad1   = (const float*)d_in[8];
    const float* b1    = (const float*)d_in[9];
    const float* gamma = (const float*)d_in[10];
    const float* beta  = (const float*)d_in[11];
    float* out = (float*)d_out;

    static cudaStream_t s2 = nullptr;
    static cudaEvent_t evF = nullptr, evJ = nullptr;
    if (s2 == nullptr) {   // infra init on first (non-captured) call; identical work every call
        cudaStreamCreateWithFlags(&s2, cudaStreamNonBlocking);
        cudaEventCreateWithFlags(&evF, cudaEventDisableTiming);
        cudaEventCreateWithFlags(&evJ, cudaEventDisableTiming);
        cudaFuncSetAttribute(gemm_mma_kernel, cudaFuncAttributeMaxDynamicSharedMemorySize, GEMM_SMEM);
    }

    zero_kernel<<<(NN + 255) / 256, 256>>>((const int*)ei);
    cudaEventRecord(evF, 0);
    cudaStreamWaitEvent(s2, evF, 0);
    // branch A (s2): conversions + GEMM (independent of graph prep)
    conv_w_kernel<<<(256 * 256 + 255) / 256, 256, 0, s2>>>(W0, W1);
    conv_x_kernel<<<(NN * 256 / 8 + 255) / 256, 256, 0, s2>>>(x);
    gemm_mma_kernel<<<dim3(391, 2), 256, GEMM_SMEM, s2>>>(as0, ad0, as1, ad1);
    cudaEventRecord(evJ, s2);
    // branch B (legacy): edge prep -> scans -> scatter
    prep_kernel<<<(EE + 255) / 256, 256>>>(ei);
    scan1_kernel<<<dim3(NBLK, 2), 1024>>>();
    scan2_kernel<<<1, 128>>>();
    scan3_kernel<<<dim3(NBLK, 2), 1024>>>();
    scatter_kernel<<<(EE + 255) / 256, 256>>>();
    // join
    cudaStreamWaitEvent(0, evJ, 0);
    agg_kernel<<<(NN + 7) / 8, 256>>>(b0, b1, x, gamma, beta, out);
}